// round 9
// baseline (speedup 1.0000x reference)
#include <cuda_runtime.h>
#include <math.h>

#define BB   128
#define HH   512
#define INDIM 256
#define EDIM 256
#define VV   20000
#define TSRC 64
#define TTRG 50
#define G3H  1536
#define KX   257
#define KSH  8
#define KSI  4
#define NBLK 148

// ---------------- scratch (device globals; no allocation) ----------------
__device__ float g_h [BB*HH];
__device__ float g_h2[BB*HH];
__device__ float g_gi_enc[(size_t)TSRC*BB*G3H];
__device__ float g_ph[(size_t)KSH*BB*G3H];
__device__ float g_pi[(size_t)KSI*BB*G3H];
__device__ float g_logits[(size_t)BB*VV];
__device__ int   g_eid[BB];
__device__ float g_rate[BB];
__device__ unsigned g_cnt = 0;
__device__ volatile unsigned g_gen = 0;

// ---- XLA f32 tanh (rational approx) + logistic expansion, no FMA fusion --
__device__ __forceinline__ float xla_tanh(float x){
    float ax = fabsf(x);
    float xc = fmaxf(-7.90531110763549805f, fminf(7.90531110763549805f, x));
    float x2 = __fmul_rn(xc, xc);
    float np = -2.76076847742355e-16f;
    np = __fadd_rn(__fmul_rn(np, x2),  2.00018790482477e-13f);
    np = __fadd_rn(__fmul_rn(np, x2), -8.60467152213735e-11f);
    np = __fadd_rn(__fmul_rn(np, x2),  5.12229709037114e-08f);
    np = __fadd_rn(__fmul_rn(np, x2),  1.48572235717979e-05f);
    np = __fadd_rn(__fmul_rn(np, x2),  6.37261928875436e-04f);
    np = __fadd_rn(__fmul_rn(np, x2),  4.89352455891786e-03f);
    np = __fmul_rn(np, xc);
    float dp = 1.19825839466702e-06f;
    dp = __fadd_rn(__fmul_rn(dp, x2), 1.18534705686654e-04f);
    dp = __fadd_rn(__fmul_rn(dp, x2), 2.26843463243900e-03f);
    dp = __fadd_rn(__fmul_rn(dp, x2), 4.89352518554385e-03f);
    float r = __fdiv_rn(np, dp);
    return (ax < 0.0004f) ? x : r;
}
__device__ __forceinline__ float xla_sigmoid(float x){
    return __fadd_rn(0.5f, __fmul_rn(0.5f, xla_tanh(__fmul_rn(0.5f, x))));
}

// ---- packed f32x2 helpers --------------------------------------------------
__device__ __forceinline__ unsigned long long packf2(float lo, float hi){
    unsigned long long r;
    asm("mov.b64 %0, {%1, %2};" : "=l"(r)
        : "r"(__float_as_uint(lo)), "r"(__float_as_uint(hi)));
    return r;
}
__device__ __forceinline__ void unpackf2(unsigned long long v, float& lo, float& hi){
    unsigned int a, b;
    asm("mov.b64 {%0, %1}, %2;" : "=r"(a), "=r"(b) : "l"(v));
    lo = __uint_as_float(a); hi = __uint_as_float(b);
}
__device__ __forceinline__ unsigned long long ffma2(
    unsigned long long a, unsigned long long b, unsigned long long c){
    unsigned long long d;
    asm("fma.rn.f32x2 %0, %1, %2, %3;" : "=l"(d) : "l"(a), "l"(b), "l"(c));
    return d;
}

// ---- generational grid barrier (all NBLK blocks co-resident) --------------
__device__ __forceinline__ void gridbar(){
    __syncthreads();
    if (threadIdx.x == 0){
        __threadfence();
        unsigned gen = g_gen;
        if (atomicAdd(&g_cnt, 1u) == NBLK-1u){
            g_cnt = 0;
            __threadfence();
            g_gen = gen + 1u;
        } else {
            while (g_gen == gen) { __nanosleep(64); }
        }
        __threadfence();
    }
    __syncthreads();
}

// ---------------- plain SGEMM (encoder-Wi precompute only) ----------------
template<int BM,int BN,int BK,int TM,int TN>
__global__ void sgemm_k(const float* __restrict__ A, int lda,
                        const float* __restrict__ W,
                        const float* __restrict__ bias,
                        float* __restrict__ C,
                        int M, int N, int K)
{
    __shared__ float As[BK][BM+4];
    __shared__ float Ws[BK][BN+4];
    constexpr int NT = (BM/TM)*(BN/TN);
    const int tx = threadIdx.x;
    const int ty = threadIdx.y;
    const int tid = ty*(BN/TN)+tx;
    const int bm0 = blockIdx.y*BM;
    const int bn0 = blockIdx.x*BN;

    float acc[TM][TN];
    #pragma unroll
    for (int i=0;i<TM;i++)
        #pragma unroll
        for (int j=0;j<TN;j++) acc[i][j]=0.f;

    for (int k0=0;k0<K;k0+=BK){
        for (int i=tid;i<BM*BK;i+=NT){
            int kl=i%BK, ml=i/BK;
            int m=bm0+ml, kg=k0+kl;
            As[kl][ml] = (m<M && kg<K) ? A[(size_t)m*lda + kg] : 0.f;
        }
        for (int i=tid;i<BN*BK;i+=NT){
            int kl=i%BK, nl=i/BK;
            int n=bn0+nl, kg=k0+kl;
            Ws[kl][nl] = (n<N && kg<K) ? W[(size_t)n*K + kg] : 0.f;
        }
        __syncthreads();
        #pragma unroll
        for (int kk=0;kk<BK;kk++){
            float a[TM], b[TN];
            #pragma unroll
            for (int i=0;i<TM;i+=4){
                float4 v = *(const float4*)&As[kk][ty*TM+i];
                a[i]=v.x; a[i+1]=v.y; a[i+2]=v.z; a[i+3]=v.w;
            }
            #pragma unroll
            for (int j=0;j<TN;j+=4){
                float4 v = *(const float4*)&Ws[kk][tx*TN+j];
                b[j]=v.x; b[j+1]=v.y; b[j+2]=v.z; b[j+3]=v.w;
            }
            #pragma unroll
            for (int i=0;i<TM;i++)
                #pragma unroll
                for (int j=0;j<TN;j++)
                    acc[i][j] = fmaf(a[i], b[j], acc[i][j]);
        }
        __syncthreads();
    }
    #pragma unroll
    for (int i=0;i<TM;i++){
        int m=bm0+ty*TM+i;
        if (m>=M) continue;
        #pragma unroll
        for (int j=0;j<TN;j++){
            int n=bn0+tx*TN+j;
            if (n<N) C[(size_t)m*N+n] = __fadd_rn(acc[i][j], bias[n]);
        }
    }
}

// ---------------- mega-kernel phases --------------------------------------

// split-K GRU GEMM partials (f32x2 over j-pairs; per-lane chains == round 8)
__device__ __forceinline__ void phase_grugemm(
    const float* __restrict__ h_in,
    const float* __restrict__ Wh,
    const float* __restrict__ Wi,     // null => encoder (H only)
    const float* __restrict__ emb,
    int nz, char* sm)
{
    float (*As)[36]  = (float(*)[36])sm;                 // 4608 B
    float (*Ws)[132] = (float(*)[132])(sm + 4608);       // 16896 B
    int*   seid  = (int*)  (sm + 21504);
    float* srate = (float*)(sm + 21632);
    const int tid = threadIdx.x;
    const int tx = tid & 15, ty = tid >> 4;
    const int ntile = (G3H/128)*(BB/32)*nz;

    for (int tt = blockIdx.x; tt < ntile; tt += NBLK){
        int zi  = tt % nz;
        int rem = tt / nz;
        int bt = rem & 3;
        int jt = rem >> 2;
        int j0 = jt*128, b0 = bt*32;
        const bool isH = (zi < KSH);
        const int  K     = isH ? HH : KX;
        const int  chunk = isH ? (HH/KSH) : 65;
        const int  ks    = isH ? zi : (zi - KSH);
        const float* W   = isH ? Wh : Wi;
        float* P         = isH ? g_ph : g_pi;
        const int kbeg = ks*chunk;
        const int kend = isH ? (kbeg+chunk) : min(KX, kbeg+chunk);

        if (!isH){
            if (tid < 32){ seid[tid] = g_eid[b0+tid]; srate[tid] = g_rate[b0+tid]; }
            __syncthreads();
        }

        unsigned long long acc2[2][4];
        #pragma unroll
        for (int i=0;i<2;i++)
            #pragma unroll
            for (int p=0;p<4;p++) acc2[i][p]=0ull;

        for (int k0=kbeg; k0<kend; k0+=32){
            #pragma unroll 4
            for (int i=tid;i<32*32;i+=256){
                int bl=i>>5, kl=i&31;
                int kg=k0+kl;
                float v=0.f;
                if (kg<kend){
                    if (isH) v = h_in[(size_t)(b0+bl)*HH + kg];
                    else     v = (kg<EDIM) ? emb[(size_t)seid[bl]*EDIM + kg] : srate[bl];
                }
                As[kl][bl]=v;
            }
            #pragma unroll 4
            for (int i=tid;i<128*32;i+=256){
                int jl=i>>5, kl=i&31;
                int kg=k0+kl;
                Ws[kl][jl] = (kg<kend) ? W[(size_t)(j0+jl)*K + kg] : 0.f;
            }
            __syncthreads();
            #pragma unroll
            for (int kk=0;kk<32;kk++){
                float2 a  = *(const float2*)&As[kk][ty*2];
                float4 w0 = *(const float4*)&Ws[kk][tx*8];
                float4 w1 = *(const float4*)&Ws[kk][tx*8+4];
                unsigned long long A0=packf2(a.x,a.x), A1=packf2(a.y,a.y);
                unsigned long long B0=packf2(w0.x,w0.y), B1=packf2(w0.z,w0.w);
                unsigned long long B2=packf2(w1.x,w1.y), B3=packf2(w1.z,w1.w);
                acc2[0][0]=ffma2(A0,B0,acc2[0][0]); acc2[1][0]=ffma2(A1,B0,acc2[1][0]);
                acc2[0][1]=ffma2(A0,B1,acc2[0][1]); acc2[1][1]=ffma2(A1,B1,acc2[1][1]);
                acc2[0][2]=ffma2(A0,B2,acc2[0][2]); acc2[1][2]=ffma2(A1,B2,acc2[1][2]);
                acc2[0][3]=ffma2(A0,B3,acc2[0][3]); acc2[1][3]=ffma2(A1,B3,acc2[1][3]);
            }
            __syncthreads();
        }
        #pragma unroll
        for (int bl=0;bl<2;bl++){
            int b = b0 + ty*2 + bl;
            float r0,r1,r2,r3,r4,r5,r6,r7;
            unpackf2(acc2[bl][0], r0,r1); unpackf2(acc2[bl][1], r2,r3);
            unpackf2(acc2[bl][2], r4,r5); unpackf2(acc2[bl][3], r6,r7);
            float* p = P + ((size_t)ks*BB + b)*G3H + j0 + tx*8;
            *(float4*)p     = make_float4(r0,r1,r2,r3);
            *(float4*)(p+4) = make_float4(r4,r5,r6,r7);
        }
    }
}

__device__ __forceinline__ void phase_gate_enc(
    const float* __restrict__ h_in, float* __restrict__ h_out,
    const float* __restrict__ bh, const float* __restrict__ gi_t,
    const int* __restrict__ src_len, int t)
{
    for (int idx = blockIdx.x*256 + threadIdx.x; idx < BB*HH; idx += NBLK*256){
        int b = idx / HH, j = idx % HH;
        float gh[3];
        #pragma unroll
        for (int g=0; g<3; g++){
            float s = 0.f;
            #pragma unroll
            for (int ks=0; ks<KSH; ks++)
                s = __fadd_rn(s, g_ph[((size_t)ks*BB + b)*G3H + g*HH + j]);
            gh[g] = __fadd_rn(s, bh[g*HH+j]);
        }
        const float* gi = gi_t + (size_t)b*G3H;
        float r = xla_sigmoid(__fadd_rn(gi[j],      gh[0]));
        float z = xla_sigmoid(__fadd_rn(gi[HH+j],   gh[1]));
        float n = xla_tanh(__fadd_rn(gi[2*HH+j], __fmul_rn(r, gh[2])));
        float hp = h_in[idx];
        float hn = __fadd_rn(__fmul_rn(__fsub_rn(1.f,z),n), __fmul_rn(z,hp));
        if (t >= src_len[b]) hn = hp;
        h_out[idx] = hn;
    }
}

__device__ __forceinline__ void phase_gate_dec(
    const float* __restrict__ h_in, float* __restrict__ h_out,
    const float* __restrict__ bi, const float* __restrict__ bh)
{
    for (int idx = blockIdx.x*256 + threadIdx.x; idx < BB*HH; idx += NBLK*256){
        int b = idx / HH, j = idx % HH;
        float gh[3], gi[3];
        #pragma unroll
        for (int g=0; g<3; g++){
            float s = 0.f;
            #pragma unroll
            for (int ks=0; ks<KSH; ks++)
                s = __fadd_rn(s, g_ph[((size_t)ks*BB + b)*G3H + g*HH + j]);
            gh[g] = __fadd_rn(s, bh[g*HH+j]);
            float si = 0.f;
            #pragma unroll
            for (int ks=0; ks<KSI; ks++)
                si = __fadd_rn(si, g_pi[((size_t)ks*BB + b)*G3H + g*HH + j]);
            gi[g] = __fadd_rn(si, bi[g*HH+j]);
        }
        float r = xla_sigmoid(__fadd_rn(gi[0], gh[0]));
        float z = xla_sigmoid(__fadd_rn(gi[1], gh[1]));
        float n = xla_tanh(__fadd_rn(gi[2], __fmul_rn(r, gh[2])));
        float hp = h_in[idx];
        float hn = __fadd_rn(__fmul_rn(__fsub_rn(1.f,z),n), __fmul_rn(z,hp));
        h_out[idx] = hn;
    }
}

__device__ __forceinline__ void phase_vgemm(
    const float* __restrict__ A, const float* __restrict__ W,
    const float* __restrict__ bias, float* __restrict__ C, char* sm)
{
    float (*As)[132] = (float(*)[132])sm;
    float (*Ws)[132] = (float(*)[132])(sm + 16896);
    const int tid = threadIdx.x;
    const int tx = tid & 15;
    const int ty = tid >> 4;
    const int NTL = (VV+127)/128;

    for (int nt = blockIdx.x; nt < NTL; nt += NBLK){
        const int bn0 = nt*128;
        unsigned long long acc2[8][4];
        #pragma unroll
        for (int i=0;i<8;i++)
            #pragma unroll
            for (int p=0;p<4;p++) acc2[i][p]=0ull;

        for (int k0=0;k0<HH;k0+=32){
            #pragma unroll 4
            for (int i=tid;i<128*32;i+=256){
                int kl=i%32, ml=i/32;
                As[kl][ml] = A[(size_t)ml*HH + k0+kl];
            }
            #pragma unroll 4
            for (int i=tid;i<128*32;i+=256){
                int kl=i%32, nl=i/32;
                int n=bn0+nl;
                Ws[kl][nl] = (n<VV) ? W[(size_t)n*HH + k0+kl] : 0.f;
            }
            __syncthreads();
            #pragma unroll
            for (int kk=0;kk<32;kk++){
                float4 a0 = *(const float4*)&As[kk][ty*8];
                float4 a1 = *(const float4*)&As[kk][ty*8+4];
                float4 b0 = *(const float4*)&Ws[kk][tx*8];
                float4 b1 = *(const float4*)&Ws[kk][tx*8+4];
                unsigned long long A2[8], B2[4];
                A2[0]=packf2(a0.x,a0.x); A2[1]=packf2(a0.y,a0.y);
                A2[2]=packf2(a0.z,a0.z); A2[3]=packf2(a0.w,a0.w);
                A2[4]=packf2(a1.x,a1.x); A2[5]=packf2(a1.y,a1.y);
                A2[6]=packf2(a1.z,a1.z); A2[7]=packf2(a1.w,a1.w);
                B2[0]=packf2(b0.x,b0.y); B2[1]=packf2(b0.z,b0.w);
                B2[2]=packf2(b1.x,b1.y); B2[3]=packf2(b1.z,b1.w);
                #pragma unroll
                for (int i=0;i<8;i++)
                    #pragma unroll
                    for (int p=0;p<4;p++)
                        acc2[i][p] = ffma2(A2[i], B2[p], acc2[i][p]);
            }
            __syncthreads();
        }
        #pragma unroll
        for (int i=0;i<8;i++){
            int m = ty*8+i;
            #pragma unroll
            for (int p=0;p<4;p++){
                float lo, hi;
                unpackf2(acc2[i][p], lo, hi);
                int n0 = bn0 + tx*8 + p*2;
                if (n0   < VV) C[(size_t)m*VV + n0  ] = __fadd_rn(lo, bias[n0  ]);
                if (n0+1 < VV) C[(size_t)m*VV + n0+1] = __fadd_rn(hi, bias[n0+1]);
            }
        }
    }
}

__device__ __forceinline__ void phase_softrate(
    float* __restrict__ out, int step, const float* __restrict__ hcur,
    const float* __restrict__ emb,
    const float* __restrict__ W1, const float* __restrict__ b1,
    const float* __restrict__ W2, const float* __restrict__ b2, char* sm)
{
    int b = blockIdx.x;
    if (b >= BB) return;
    int tid = threadIdx.x;
    float*  sv  = (float*) sm;            // 1024
    int*    si  = (int*)  (sm + 1024);    // 1024
    double* sd  = (double*)(sm + 2048);   // 2048
    float*  xc  = (float*)(sm + 4096);    // 3072
    double* red = (double*)(sm + 7168);   // 2048

    const float* row = g_logits + (size_t)b*VV;
    // row max
    float m = -3.4e38f;
    for (int k=tid;k<VV;k+=256) m = fmaxf(m, row[k]);
    sv[tid]=m; __syncthreads();
    for (int s=128;s>0;s>>=1){ if (tid<s) sv[tid]=fmaxf(sv[tid],sv[tid+s]); __syncthreads(); }
    float mx = sv[0];
    __syncthreads();
    // sum exp
    float ps=0.f; double pd=0.0; int cnt=0;
    for (int k=tid;k<VV;k+=256){
        ps += expf(__fsub_rn(row[k], mx));
        if (++cnt==16){ pd += (double)ps; ps=0.f; cnt=0; }
    }
    pd += (double)ps;
    sd[tid]=pd; __syncthreads();
    for (int st=128;st>0;st>>=1){ if (tid<st) sd[tid]+=sd[tid+st]; __syncthreads(); }
    float lsh = logf((float)sd[0]);
    // write logp + argmax over written values
    float* o = out + ((size_t)step*BB + b)*VV;
    float bm = -3.4e38f; int bi_ = VV;
    for (int k=tid;k<VV;k+=256){
        float v = __fsub_rn(__fsub_rn(row[k], mx), lsh);
        o[k] = v;
        if (v>bm || (v==bm && k<bi_)){ bm=v; bi_=k; }
    }
    sv[tid]=bm; si[tid]=bi_; __syncthreads();
    for (int s=128;s>0;s>>=1){
        if (tid<s){
            float v2=sv[tid+s]; int i2=si[tid+s];
            if (v2>sv[tid] || (v2==sv[tid] && i2<si[tid])){ sv[tid]=v2; si[tid]=i2; }
        }
        __syncthreads();
    }
    int e = si[0];
    if (tid==0) g_eid[b] = e;
    __syncthreads();

    // rate head
    if (tid < EDIM) xc[tid] = emb[(size_t)e*EDIM + tid];
    for (int k=tid;k<HH;k+=256) xc[EDIM+k] = hcur[(size_t)b*HH + k];
    __syncthreads();
    double partial = 0.0;
    for (int j=tid;j<HH;j+=256){
        const float* w = W1 + (size_t)j*(EDIM+HH);
        float acc = 0.f;
        #pragma unroll 8
        for (int k=0;k<EDIM+HH;k+=4){
            float4 wv = *(const float4*)(w+k);
            acc = fmaf(wv.x, xc[k],   acc);
            acc = fmaf(wv.y, xc[k+1], acc);
            acc = fmaf(wv.z, xc[k+2], acc);
            acc = fmaf(wv.w, xc[k+3], acc);
        }
        float pre = __fadd_rn(acc, b1[j]);
        partial += (double)__fmul_rn(fmaxf(pre, 0.f), W2[j]);
    }
    red[tid]=partial; __syncthreads();
    for (int s=128;s>0;s>>=1){ if (tid<s) red[tid]+=red[tid+s]; __syncthreads(); }
    if (tid==0){
        float y = __fadd_rn((float)red[0], b2[0]);
        float pr = xla_sigmoid(y);
        out[(size_t)TTRG*BB*VV + step*BB + b] = pr;
        g_rate[b] = pr;
    }
}

// ---------------- the persistent megakernel -------------------------------
__global__ __launch_bounds__(256) void mega_k(
    const int*   __restrict__ src_len,
    const int*   __restrict__ trg_eid,
    const float* __restrict__ trg_rate,
    const float* __restrict__ emb,
    const float* __restrict__ enc_Wh, const float* __restrict__ enc_bh,
    const float* __restrict__ dec_Wi, const float* __restrict__ dec_Wh,
    const float* __restrict__ dec_bi, const float* __restrict__ dec_bh,
    const float* __restrict__ We,     const float* __restrict__ be,
    const float* __restrict__ W1,     const float* __restrict__ b1,
    const float* __restrict__ W2,     const float* __restrict__ b2,
    float* __restrict__ out)
{
    __shared__ __align__(16) char SM[33792];
    const int tid = threadIdx.x;
    const int bid = blockIdx.x;

    // phase 0: init (zero step-0 outputs, h=0, seed decoder carry)
    {
        const size_t RATE_OFF = (size_t)TTRG*BB*VV;
        for (size_t i = (size_t)bid*256+tid; i < (size_t)BB*VV; i += (size_t)NBLK*256)
            out[i] = 0.f;
        for (int i = bid*256+tid; i < BB*HH; i += NBLK*256) g_h[i] = 0.f;
        if (bid==0 && tid<BB){
            out[RATE_OFF+tid] = 0.f;
            g_eid[tid]  = trg_eid[tid];
            g_rate[tid] = trg_rate[tid];
        }
        gridbar();
    }

    float* hA = g_h;
    float* hB = g_h2;

    // encoder
    for (int t=0;t<TSRC;t++){
        phase_grugemm(hA, enc_Wh, nullptr, emb, KSH, SM);
        gridbar();
        phase_gate_enc(hA, hB, enc_bh, g_gi_enc + (size_t)t*BB*G3H, src_len, t);
        gridbar();
        float* tmp=hA; hA=hB; hB=tmp;
    }

    // decoder
    for (int step=1; step<TTRG; step++){
        phase_grugemm(hA, dec_Wh, dec_Wi, emb, KSH+KSI, SM);
        gridbar();
        phase_gate_dec(hA, hB, dec_bi, dec_bh);
        gridbar();
        float* tmp=hA; hA=hB; hB=tmp;
        phase_vgemm(hA, We, be, g_logits, SM);
        gridbar();
        phase_softrate(out, step, hA, emb, W1, b1, W2, b2, SM);
        gridbar();
    }
}

// ---------------- launch -----------------------------------------------
extern "C" void kernel_launch(void* const* d_in, const int* in_sizes, int n_in,
                              void* d_out, int out_size)
{
    const float* src      = (const float*)d_in[0];
    const int*   src_len  = (const int*)  d_in[1];
    const int*   trg_eid  = (const int*)  d_in[2];
    const float* trg_rate = (const float*)d_in[3];
    const float* emb      = (const float*)d_in[4];
    const float* enc_Wi   = (const float*)d_in[5];
    const float* enc_Wh   = (const float*)d_in[6];
    const float* enc_bi   = (const float*)d_in[7];
    const float* enc_bh   = (const float*)d_in[8];
    const float* dec_Wi   = (const float*)d_in[9];
    const float* dec_Wh   = (const float*)d_in[10];
    const float* dec_bi   = (const float*)d_in[11];
    const float* dec_bh   = (const float*)d_in[12];
    const float* We       = (const float*)d_in[13];
    const float* be       = (const float*)d_in[14];
    const float* W1       = (const float*)d_in[15];
    const float* b1       = (const float*)d_in[16];
    const float* W2       = (const float*)d_in[17];
    const float* b2       = (const float*)d_in[18];
    float* out = (float*)d_out;

    float* p_gi_enc;
    cudaGetSymbolAddress((void**)&p_gi_enc, g_gi_enc);

    // Encoder-Wi precompute (parallel GEMM; independent of megakernel init)
    sgemm_k<64,64,32,4,4><<<dim3(G3H/64, (TSRC*BB)/64), dim3(16,16)>>>(
        src, INDIM, enc_Wi, enc_bi, p_gi_enc, TSRC*BB, G3H, INDIM);

    // Everything else: one persistent kernel with internal grid barriers
    mega_k<<<NBLK, 256>>>(
        src_len, trg_eid, trg_rate, emb,
        enc_Wh, enc_bh,
        dec_Wi, dec_Wh, dec_bi, dec_bh,
        We, be, W1, b1, W2, b2, out);
}

// round 10
// speedup vs baseline: 1.5703x; 1.5703x over previous
#include <cuda_runtime.h>
#include <math.h>

#define BB   128
#define HH   512
#define INDIM 256
#define EDIM 256
#define VV   20000
#define TSRC 64
#define TTRG 50
#define G3H  1536
#define KX   257

// ---------------- scratch (device globals; no allocation) ----------------
__device__ float g_h [BB*HH];
__device__ float g_h2[BB*HH];
__device__ float g_gi_enc[(size_t)TSRC*BB*G3H];
__device__ float g_logits[(size_t)BB*VV];
__device__ int   g_eid[BB];
__device__ float g_rate[BB];

// ---- XLA f32 tanh (rational approx) + logistic expansion, no FMA fusion --
__device__ __forceinline__ float xla_tanh(float x){
    float ax = fabsf(x);
    float xc = fmaxf(-7.90531110763549805f, fminf(7.90531110763549805f, x));
    float x2 = __fmul_rn(xc, xc);
    float np = -2.76076847742355e-16f;
    np = __fadd_rn(__fmul_rn(np, x2),  2.00018790482477e-13f);
    np = __fadd_rn(__fmul_rn(np, x2), -8.60467152213735e-11f);
    np = __fadd_rn(__fmul_rn(np, x2),  5.12229709037114e-08f);
    np = __fadd_rn(__fmul_rn(np, x2),  1.48572235717979e-05f);
    np = __fadd_rn(__fmul_rn(np, x2),  6.37261928875436e-04f);
    np = __fadd_rn(__fmul_rn(np, x2),  4.89352455891786e-03f);
    np = __fmul_rn(np, xc);
    float dp = 1.19825839466702e-06f;
    dp = __fadd_rn(__fmul_rn(dp, x2), 1.18534705686654e-04f);
    dp = __fadd_rn(__fmul_rn(dp, x2), 2.26843463243900e-03f);
    dp = __fadd_rn(__fmul_rn(dp, x2), 4.89352518554385e-03f);
    float r = __fdiv_rn(np, dp);
    return (ax < 0.0004f) ? x : r;
}
__device__ __forceinline__ float xla_sigmoid(float x){
    return __fadd_rn(0.5f, __fmul_rn(0.5f, xla_tanh(__fmul_rn(0.5f, x))));
}

// ---- packed f32x2 helpers --------------------------------------------------
__device__ __forceinline__ unsigned long long packf2(float lo, float hi){
    unsigned long long r;
    asm("mov.b64 %0, {%1, %2};" : "=l"(r)
        : "r"(__float_as_uint(lo)), "r"(__float_as_uint(hi)));
    return r;
}
__device__ __forceinline__ void unpackf2(unsigned long long v, float& lo, float& hi){
    unsigned int a, b;
    asm("mov.b64 {%0, %1}, %2;" : "=r"(a), "=r"(b) : "l"(v));
    lo = __uint_as_float(a); hi = __uint_as_float(b);
}
__device__ __forceinline__ unsigned long long ffma2(
    unsigned long long a, unsigned long long b, unsigned long long c){
    unsigned long long d;
    asm("fma.rn.f32x2 %0, %1, %2, %3;" : "=l"(d) : "l"(a), "l"(b), "l"(c));
    return d;
}

// ---------------- plain SGEMM (encoder-Wi precompute only) ----------------
template<int BM,int BN,int BK,int TM,int TN>
__global__ void sgemm_k(const float* __restrict__ A, int lda,
                        const float* __restrict__ W,
                        const float* __restrict__ bias,
                        float* __restrict__ C,
                        int M, int N, int K)
{
    __shared__ float As[BK][BM+4];
    __shared__ float Ws[BK][BN+4];
    constexpr int NT = (BM/TM)*(BN/TN);
    const int tx = threadIdx.x;
    const int ty = threadIdx.y;
    const int tid = ty*(BN/TN)+tx;
    const int bm0 = blockIdx.y*BM;
    const int bn0 = blockIdx.x*BN;

    float acc[TM][TN];
    #pragma unroll
    for (int i=0;i<TM;i++)
        #pragma unroll
        for (int j=0;j<TN;j++) acc[i][j]=0.f;

    for (int k0=0;k0<K;k0+=BK){
        for (int i=tid;i<BM*BK;i+=NT){
            int kl=i%BK, ml=i/BK;
            int m=bm0+ml, kg=k0+kl;
            As[kl][ml] = (m<M && kg<K) ? A[(size_t)m*lda + kg] : 0.f;
        }
        for (int i=tid;i<BN*BK;i+=NT){
            int kl=i%BK, nl=i/BK;
            int n=bn0+nl, kg=k0+kl;
            Ws[kl][nl] = (n<N && kg<K) ? W[(size_t)n*K + kg] : 0.f;
        }
        __syncthreads();
        #pragma unroll
        for (int kk=0;kk<BK;kk++){
            float a[TM], b[TN];
            #pragma unroll
            for (int i=0;i<TM;i+=4){
                float4 v = *(const float4*)&As[kk][ty*TM+i];
                a[i]=v.x; a[i+1]=v.y; a[i+2]=v.z; a[i+3]=v.w;
            }
            #pragma unroll
            for (int j=0;j<TN;j+=4){
                float4 v = *(const float4*)&Ws[kk][tx*TN+j];
                b[j]=v.x; b[j+1]=v.y; b[j+2]=v.z; b[j+3]=v.w;
            }
            #pragma unroll
            for (int i=0;i<TM;i++)
                #pragma unroll
                for (int j=0;j<TN;j++)
                    acc[i][j] = fmaf(a[i], b[j], acc[i][j]);
        }
        __syncthreads();
    }
    #pragma unroll
    for (int i=0;i<TM;i++){
        int m=bm0+ty*TM+i;
        if (m>=M) continue;
        #pragma unroll
        for (int j=0;j<TN;j++){
            int n=bn0+tx*TN+j;
            if (n<N) C[(size_t)m*N+n] = __fadd_rn(acc[i][j], bias[n]);
        }
    }
}

// ============ fully-fused GRU step kernels ==================================
// Tile: 64 hidden-j x 32 batch, ALL 3 gate rows computed in-block -> gate
// epilogue is block-local. 512 threads: tx=j-pair (0..31), ty=b-pair (0..15).
// FFMA2 lanes = (j, j+1); each lane is a sequential k-ascending fmaf chain.

// encoder: gh GEMM (K=512) + gate + mask. gi precomputed in g_gi_enc.
__global__ __launch_bounds__(512) void gru_enc_f(
    const float* __restrict__ h_in, float* __restrict__ h_out,
    const float* __restrict__ Wh, const float* __restrict__ bh,
    const float* __restrict__ gi_t,
    const int* __restrict__ src_len, int t)
{
    __shared__ unsigned long long As2[32][34];      // dup(h[b][k])
    __shared__ unsigned long long Ws2[3][32][34];   // pair(W[g,j],W[g,j+1])[k]
    const int tid = threadIdx.x;
    const int tx = tid & 31;      // j-pair
    const int ty = tid >> 5;      // b-pair
    const int j0 = blockIdx.x*64;
    const int b0 = blockIdx.y*32;

    unsigned long long acc[2][3];
    #pragma unroll
    for (int i=0;i<2;i++)
        #pragma unroll
        for (int g=0;g<3;g++) acc[i][g]=0ull;

    for (int k0=0;k0<HH;k0+=32){
        #pragma unroll
        for (int i=tid;i<32*32;i+=512){
            int kl=i&31, bl=i>>5;
            float v = h_in[(size_t)(b0+bl)*HH + k0+kl];
            As2[kl][bl] = packf2(v,v);
        }
        #pragma unroll
        for (int i=tid;i<3*32*32;i+=512){
            int kl=i&31, r=i>>5;
            int jp=r&31, g=r>>5;
            size_t row = (size_t)(g*HH + j0 + 2*jp)*HH + k0+kl;
            Ws2[g][kl][jp] = packf2(Wh[row], Wh[row+HH]);
        }
        __syncthreads();
        #pragma unroll
        for (int kk=0;kk<32;kk++){
            ulonglong2 av = *(const ulonglong2*)&As2[kk][2*ty];
            unsigned long long w0=Ws2[0][kk][tx], w1=Ws2[1][kk][tx], w2=Ws2[2][kk][tx];
            acc[0][0]=ffma2(av.x,w0,acc[0][0]); acc[1][0]=ffma2(av.y,w0,acc[1][0]);
            acc[0][1]=ffma2(av.x,w1,acc[0][1]); acc[1][1]=ffma2(av.y,w1,acc[1][1]);
            acc[0][2]=ffma2(av.x,w2,acc[0][2]); acc[1][2]=ffma2(av.y,w2,acc[1][2]);
        }
        __syncthreads();
    }
    // epilogue: gate for (b, j) and (b, j+1)
    const int j = j0 + 2*tx;
    float bhr0=bh[j],      bhr1=bh[j+1];
    float bhz0=bh[HH+j],   bhz1=bh[HH+j+1];
    float bhn0=bh[2*HH+j], bhn1=bh[2*HH+j+1];
    #pragma unroll
    for (int bl=0; bl<2; bl++){
        int b = b0 + 2*ty + bl;
        const float* gi = gi_t + (size_t)b*G3H;
        float dr0,dr1,dz0,dz1,dn0,dn1;
        unpackf2(acc[bl][0], dr0,dr1);
        unpackf2(acc[bl][1], dz0,dz1);
        unpackf2(acc[bl][2], dn0,dn1);
        int frozen = (t >= src_len[b]);
        #pragma unroll
        for (int jj=0;jj<2;jj++){
            float gr = __fadd_rn(jj?dr1:dr0, jj?bhr1:bhr0);
            float gz = __fadd_rn(jj?dz1:dz0, jj?bhz1:bhz0);
            float gn = __fadd_rn(jj?dn1:dn0, jj?bhn1:bhn0);
            float r = xla_sigmoid(__fadd_rn(gi[j+jj],      gr));
            float z = xla_sigmoid(__fadd_rn(gi[HH+j+jj],   gz));
            float n = xla_tanh(__fadd_rn(gi[2*HH+j+jj], __fmul_rn(r, gn)));
            float hp = h_in[(size_t)b*HH + j+jj];
            float hn = __fadd_rn(__fmul_rn(__fsub_rn(1.f,z),n), __fmul_rn(z,hp));
            h_out[(size_t)b*HH + j+jj] = frozen ? hp : hn;
        }
    }
}

// decoder: gi GEMM (K=257 incl. rate tail) + gh GEMM (K=512) + gate.
__global__ __launch_bounds__(512) void gru_dec_f(
    const float* __restrict__ h_in, float* __restrict__ h_out,
    const float* __restrict__ Wi, const float* __restrict__ bi,
    const float* __restrict__ Wh, const float* __restrict__ bh,
    const float* __restrict__ emb)
{
    __shared__ unsigned long long As2[32][34];
    __shared__ unsigned long long Ws2[3][32][34];
    __shared__ int   seid[32];
    __shared__ float srate[32];
    const int tid = threadIdx.x;
    const int tx = tid & 31;
    const int ty = tid >> 5;
    const int j0 = blockIdx.x*64;
    const int b0 = blockIdx.y*32;

    if (tid < 32){ seid[tid] = g_eid[b0+tid]; srate[tid] = g_rate[b0+tid]; }
    __syncthreads();

    unsigned long long acci[2][3], acch[2][3];
    #pragma unroll
    for (int i=0;i<2;i++)
        #pragma unroll
        for (int g=0;g<3;g++){ acci[i][g]=0ull; acch[i][g]=0ull; }

    // phase 1: gi over x = emb[eid[b]][0..255] (k=256 rate tail added later)
    for (int k0=0;k0<EDIM;k0+=32){
        #pragma unroll
        for (int i=tid;i<32*32;i+=512){
            int kl=i&31, bl=i>>5;
            float v = emb[(size_t)seid[bl]*EDIM + k0+kl];
            As2[kl][bl] = packf2(v,v);
        }
        #pragma unroll
        for (int i=tid;i<3*32*32;i+=512){
            int kl=i&31, r=i>>5;
            int jp=r&31, g=r>>5;
            size_t row = (size_t)(g*HH + j0 + 2*jp)*KX + k0+kl;
            Ws2[g][kl][jp] = packf2(Wi[row], Wi[row+KX]);
        }
        __syncthreads();
        #pragma unroll
        for (int kk=0;kk<32;kk++){
            ulonglong2 av = *(const ulonglong2*)&As2[kk][2*ty];
            unsigned long long w0=Ws2[0][kk][tx], w1=Ws2[1][kk][tx], w2=Ws2[2][kk][tx];
            acci[0][0]=ffma2(av.x,w0,acci[0][0]); acci[1][0]=ffma2(av.y,w0,acci[1][0]);
            acci[0][1]=ffma2(av.x,w1,acci[0][1]); acci[1][1]=ffma2(av.y,w1,acci[1][1]);
            acci[0][2]=ffma2(av.x,w2,acci[0][2]); acci[1][2]=ffma2(av.y,w2,acci[1][2]);
        }
        __syncthreads();
    }
    // rate tail: k = 256
    {
        const int j = j0 + 2*tx;
        #pragma unroll
        for (int g=0; g<3; g++){
            float wt0 = Wi[(size_t)(g*HH + j)*KX + 256];
            float wt1 = Wi[(size_t)(g*HH + j+1)*KX + 256];
            unsigned long long wt = packf2(wt0, wt1);
            #pragma unroll
            for (int bl=0; bl<2; bl++){
                float rv = srate[2*ty+bl];
                acci[bl][g] = ffma2(packf2(rv,rv), wt, acci[bl][g]);
            }
        }
    }
    // phase 2: gh over h (K=512)
    for (int k0=0;k0<HH;k0+=32){
        #pragma unroll
        for (int i=tid;i<32*32;i+=512){
            int kl=i&31, bl=i>>5;
            float v = h_in[(size_t)(b0+bl)*HH + k0+kl];
            As2[kl][bl] = packf2(v,v);
        }
        #pragma unroll
        for (int i=tid;i<3*32*32;i+=512){
            int kl=i&31, r=i>>5;
            int jp=r&31, g=r>>5;
            size_t row = (size_t)(g*HH + j0 + 2*jp)*HH + k0+kl;
            Ws2[g][kl][jp] = packf2(Wh[row], Wh[row+HH]);
        }
        __syncthreads();
        #pragma unroll
        for (int kk=0;kk<32;kk++){
            ulonglong2 av = *(const ulonglong2*)&As2[kk][2*ty];
            unsigned long long w0=Ws2[0][kk][tx], w1=Ws2[1][kk][tx], w2=Ws2[2][kk][tx];
            acch[0][0]=ffma2(av.x,w0,acch[0][0]); acch[1][0]=ffma2(av.y,w0,acch[1][0]);
            acch[0][1]=ffma2(av.x,w1,acch[0][1]); acch[1][1]=ffma2(av.y,w1,acch[1][1]);
            acch[0][2]=ffma2(av.x,w2,acch[0][2]); acch[1][2]=ffma2(av.y,w2,acch[1][2]);
        }
        __syncthreads();
    }
    // epilogue
    const int j = j0 + 2*tx;
    #pragma unroll
    for (int bl=0; bl<2; bl++){
        int b = b0 + 2*ty + bl;
        float ir0,ir1,iz0,iz1,in0,in1, hr0,hr1,hz0,hz1,hn0,hn1;
        unpackf2(acci[bl][0], ir0,ir1);
        unpackf2(acci[bl][1], iz0,iz1);
        unpackf2(acci[bl][2], in0,in1);
        unpackf2(acch[bl][0], hr0,hr1);
        unpackf2(acch[bl][1], hz0,hz1);
        unpackf2(acch[bl][2], hn0,hn1);
        #pragma unroll
        for (int jj=0;jj<2;jj++){
            float giR = __fadd_rn(jj?ir1:ir0, bi[j+jj]);
            float giZ = __fadd_rn(jj?iz1:iz0, bi[HH+j+jj]);
            float giN = __fadd_rn(jj?in1:in0, bi[2*HH+j+jj]);
            float ghR = __fadd_rn(jj?hr1:hr0, bh[j+jj]);
            float ghZ = __fadd_rn(jj?hz1:hz0, bh[HH+j+jj]);
            float ghN = __fadd_rn(jj?hn1:hn0, bh[2*HH+j+jj]);
            float r = xla_sigmoid(__fadd_rn(giR, ghR));
            float z = xla_sigmoid(__fadd_rn(giZ, ghZ));
            float n = xla_tanh(__fadd_rn(giN, __fmul_rn(r, ghN)));
            float hp = h_in[(size_t)b*HH + j+jj];
            float hn = __fadd_rn(__fmul_rn(__fsub_rn(1.f,z),n), __fmul_rn(z,hp));
            h_out[(size_t)b*HH + j+jj] = hn;
        }
    }
}

// ---------------- vocab GEMM: logits[128,20000] = h @ We^T + be (FFMA2) ---
__global__ __launch_bounds__(256) void vgemm_k(const float* __restrict__ A,
                                               const float* __restrict__ W,
                                               const float* __restrict__ bias,
                                               float* __restrict__ C)
{
    __shared__ float As[32][132];
    __shared__ float Ws[32][132];
    const int tx = threadIdx.x;
    const int ty = threadIdx.y;
    const int tid = ty*16+tx;
    const int bn0 = blockIdx.x*128;

    unsigned long long acc2[8][4];
    #pragma unroll
    for (int i=0;i<8;i++)
        #pragma unroll
        for (int p=0;p<4;p++) acc2[i][p]=0ull;

    for (int k0=0;k0<HH;k0+=32){
        #pragma unroll 4
        for (int i=tid;i<128*32;i+=256){
            int kl=i%32, ml=i/32;
            As[kl][ml] = A[(size_t)ml*HH + k0+kl];
        }
        #pragma unroll 4
        for (int i=tid;i<128*32;i+=256){
            int kl=i%32, nl=i/32;
            int n=bn0+nl;
            Ws[kl][nl] = (n<VV) ? W[(size_t)n*HH + k0+kl] : 0.f;
        }
        __syncthreads();
        #pragma unroll
        for (int kk=0;kk<32;kk++){
            float4 a0 = *(const float4*)&As[kk][ty*8];
            float4 a1 = *(const float4*)&As[kk][ty*8+4];
            float4 b0 = *(const float4*)&Ws[kk][tx*8];
            float4 b1 = *(const float4*)&Ws[kk][tx*8+4];
            unsigned long long A2[8], B2[4];
            A2[0]=packf2(a0.x,a0.x); A2[1]=packf2(a0.y,a0.y);
            A2[2]=packf2(a0.z,a0.z); A2[3]=packf2(a0.w,a0.w);
            A2[4]=packf2(a1.x,a1.x); A2[5]=packf2(a1.y,a1.y);
            A2[6]=packf2(a1.z,a1.z); A2[7]=packf2(a1.w,a1.w);
            B2[0]=packf2(b0.x,b0.y); B2[1]=packf2(b0.z,b0.w);
            B2[2]=packf2(b1.x,b1.y); B2[3]=packf2(b1.z,b1.w);
            #pragma unroll
            for (int i=0;i<8;i++)
                #pragma unroll
                for (int p=0;p<4;p++)
                    acc2[i][p] = ffma2(A2[i], B2[p], acc2[i][p]);
        }
        __syncthreads();
    }
    #pragma unroll
    for (int i=0;i<8;i++){
        int m = ty*8+i;
        #pragma unroll
        for (int p=0;p<4;p++){
            float lo, hi;
            unpackf2(acc2[i][p], lo, hi);
            int n0 = bn0 + tx*8 + p*2;
            if (n0   < VV) C[(size_t)m*VV + n0  ] = __fadd_rn(lo, bias[n0  ]);
            if (n0+1 < VV) C[(size_t)m*VV + n0+1] = __fadd_rn(hi, bias[n0+1]);
        }
    }
}

// ---------------- fused softmax (logp + argmax) + rate head ---------------
__global__ __launch_bounds__(256) void softrate_k(
    float* __restrict__ out, int step, const float* __restrict__ hcur,
    const float* __restrict__ emb,
    const float* __restrict__ W1, const float* __restrict__ b1,
    const float* __restrict__ W2, const float* __restrict__ b2)
{
    int b = blockIdx.x, tid = threadIdx.x;
    __shared__ float  sv[256];
    __shared__ int    si[256];
    __shared__ double sd[256];
    __shared__ float  xc[EDIM+HH];
    __shared__ double red[256];

    const float* row = g_logits + (size_t)b*VV;
    float m = -3.4e38f;
    for (int k=tid;k<VV;k+=256) m = fmaxf(m, row[k]);
    sv[tid]=m; __syncthreads();
    for (int s=128;s>0;s>>=1){ if (tid<s) sv[tid]=fmaxf(sv[tid],sv[tid+s]); __syncthreads(); }
    float mx = sv[0];
    __syncthreads();
    float ps=0.f; double pd=0.0; int cnt=0;
    for (int k=tid;k<VV;k+=256){
        ps += expf(__fsub_rn(row[k], mx));
        if (++cnt==16){ pd += (double)ps; ps=0.f; cnt=0; }
    }
    pd += (double)ps;
    sd[tid]=pd; __syncthreads();
    for (int st=128;st>0;st>>=1){ if (tid<st) sd[tid]+=sd[tid+st]; __syncthreads(); }
    float lsh = logf((float)sd[0]);
    float* o = out + ((size_t)step*BB + b)*VV;
    float bm = -3.4e38f; int bi_ = VV;
    for (int k=tid;k<VV;k+=256){
        float v = __fsub_rn(__fsub_rn(row[k], mx), lsh);
        o[k] = v;
        if (v>bm || (v==bm && k<bi_)){ bm=v; bi_=k; }
    }
    sv[tid]=bm; si[tid]=bi_; __syncthreads();
    for (int s=128;s>0;s>>=1){
        if (tid<s){
            float v2=sv[tid+s]; int i2=si[tid+s];
            if (v2>sv[tid] || (v2==sv[tid] && i2<si[tid])){ sv[tid]=v2; si[tid]=i2; }
        }
        __syncthreads();
    }
    int e = si[0];
    if (tid==0) g_eid[b] = e;
    __syncthreads();

    // rate head
    if (tid < EDIM) xc[tid] = emb[(size_t)e*EDIM + tid];
    for (int k=tid;k<HH;k+=256) xc[EDIM+k] = hcur[(size_t)b*HH + k];
    __syncthreads();
    double partial = 0.0;
    for (int j=tid;j<HH;j+=256){
        const float* w = W1 + (size_t)j*(EDIM+HH);
        float acc = 0.f;
        #pragma unroll 8
        for (int k=0;k<EDIM+HH;k+=4){
            float4 wv = *(const float4*)(w+k);
            acc = fmaf(wv.x, xc[k],   acc);
            acc = fmaf(wv.y, xc[k+1], acc);
            acc = fmaf(wv.z, xc[k+2], acc);
            acc = fmaf(wv.w, xc[k+3], acc);
        }
        float pre = __fadd_rn(acc, b1[j]);
        partial += (double)__fmul_rn(fmaxf(pre, 0.f), W2[j]);
    }
    red[tid]=partial; __syncthreads();
    for (int s=128;s>0;s>>=1){ if (tid<s) red[tid]+=red[tid+s]; __syncthreads(); }
    if (tid==0){
        float y = __fadd_rn((float)red[0], b2[0]);
        float pr = xla_sigmoid(y);
        out[(size_t)TTRG*BB*VV + step*BB + b] = pr;
        g_rate[b] = pr;
    }
}

// ---------------- init ----------------------------------------------------
__global__ void init_k(float* __restrict__ out, const int* __restrict__ trg_eid,
                       const float* __restrict__ trg_rate)
{
    long long i = (long long)blockIdx.x*blockDim.x + threadIdx.x;
    const long long RATE_OFF = (long long)TTRG*BB*VV;
    if (i < (long long)BB*VV) out[i] = 0.f;
    if (i < BB)               out[RATE_OFF + i] = 0.f;
    if (i < BB*HH)            g_h[i] = 0.f;
    if (i < BB){ g_eid[i] = trg_eid[i]; g_rate[i] = trg_rate[i]; }
}

// ---------------- launch ---------------------------------------------------
extern "C" void kernel_launch(void* const* d_in, const int* in_sizes, int n_in,
                              void* d_out, int out_size)
{
    const float* src      = (const float*)d_in[0];
    const int*   src_len  = (const int*)  d_in[1];
    const int*   trg_eid  = (const int*)  d_in[2];
    const float* trg_rate = (const float*)d_in[3];
    const float* emb      = (const float*)d_in[4];
    const float* enc_Wi   = (const float*)d_in[5];
    const float* enc_Wh   = (const float*)d_in[6];
    const float* enc_bi   = (const float*)d_in[7];
    const float* enc_bh   = (const float*)d_in[8];
    const float* dec_Wi   = (const float*)d_in[9];
    const float* dec_Wh   = (const float*)d_in[10];
    const float* dec_bi   = (const float*)d_in[11];
    const float* dec_bh   = (const float*)d_in[12];
    const float* We       = (const float*)d_in[13];
    const float* be       = (const float*)d_in[14];
    const float* W1       = (const float*)d_in[15];
    const float* b1       = (const float*)d_in[16];
    const float* W2       = (const float*)d_in[17];
    const float* b2       = (const float*)d_in[18];
    float* out = (float*)d_out;

    float *p_h, *p_h2, *p_gi_enc, *p_logits;
    cudaGetSymbolAddress((void**)&p_h,      g_h);
    cudaGetSymbolAddress((void**)&p_h2,     g_h2);
    cudaGetSymbolAddress((void**)&p_gi_enc, g_gi_enc);
    cudaGetSymbolAddress((void**)&p_logits, g_logits);

    float* hb[2] = {p_h, p_h2};
    int par = 0;

    init_k<<<10000,256>>>(out, trg_eid, trg_rate);

    // Encoder-Wi precompute (one big parallel GEMM)
    sgemm_k<64,64,32,4,4><<<dim3(G3H/64, (TSRC*BB)/64), dim3(16,16)>>>(
        src, INDIM, enc_Wi, enc_bi, p_gi_enc, TSRC*BB, G3H, INDIM);

    // Encoder recurrence: one fused kernel per step
    for (int t=0;t<TSRC;t++){
        gru_enc_f<<<dim3(HH/64, BB/32), 512>>>(
            hb[par], hb[par^1], enc_Wh, enc_bh,
            p_gi_enc + (size_t)t*BB*G3H, src_len, t);
        par ^= 1;
    }

    // Decoder: fused GRU + vocab GEMM + fused softmax/rate per step
    for (int step=1; step<TTRG; step++){
        gru_dec_f<<<dim3(HH/64, BB/32), 512>>>(
            hb[par], hb[par^1], dec_Wi, dec_bi, dec_Wh, dec_bh, emb);
        par ^= 1;
        vgemm_k<<<(VV+127)/128, dim3(16,16)>>>(hb[par], We, be, p_logits);
        softrate_k<<<BB,256>>>(out, step, hb[par], emb, W1, b1, W2, b2);
    }
}

// round 11
// speedup vs baseline: 1.8454x; 1.1752x over previous
#include <cuda_runtime.h>
#include <math.h>

#define BB   128
#define HH   512
#define INDIM 256
#define EDIM 256
#define VV   20000
#define TSRC 64
#define TTRG 50
#define G3H  1536
#define KX   257

// ---------------- scratch (device globals; no allocation) ----------------
__device__ float g_h [BB*HH];
__device__ float g_h2[BB*HH];
__device__ float g_gi_enc[(size_t)TSRC*BB*G3H];
__device__ float g_logits[(size_t)BB*VV];
__device__ int   g_eid[BB];
__device__ float g_rate[BB];

// ---- XLA f32 tanh (rational approx) + logistic expansion, no FMA fusion --
__device__ __forceinline__ float xla_tanh(float x){
    float ax = fabsf(x);
    float xc = fmaxf(-7.90531110763549805f, fminf(7.90531110763549805f, x));
    float x2 = __fmul_rn(xc, xc);
    float np = -2.76076847742355e-16f;
    np = __fadd_rn(__fmul_rn(np, x2),  2.00018790482477e-13f);
    np = __fadd_rn(__fmul_rn(np, x2), -8.60467152213735e-11f);
    np = __fadd_rn(__fmul_rn(np, x2),  5.12229709037114e-08f);
    np = __fadd_rn(__fmul_rn(np, x2),  1.48572235717979e-05f);
    np = __fadd_rn(__fmul_rn(np, x2),  6.37261928875436e-04f);
    np = __fadd_rn(__fmul_rn(np, x2),  4.89352455891786e-03f);
    np = __fmul_rn(np, xc);
    float dp = 1.19825839466702e-06f;
    dp = __fadd_rn(__fmul_rn(dp, x2), 1.18534705686654e-04f);
    dp = __fadd_rn(__fmul_rn(dp, x2), 2.26843463243900e-03f);
    dp = __fadd_rn(__fmul_rn(dp, x2), 4.89352518554385e-03f);
    float r = __fdiv_rn(np, dp);
    return (ax < 0.0004f) ? x : r;
}
__device__ __forceinline__ float xla_sigmoid(float x){
    return __fadd_rn(0.5f, __fmul_rn(0.5f, xla_tanh(__fmul_rn(0.5f, x))));
}

// ---- packed f32x2 helpers --------------------------------------------------
__device__ __forceinline__ unsigned long long packf2(float lo, float hi){
    unsigned long long r;
    asm("mov.b64 %0, {%1, %2};" : "=l"(r)
        : "r"(__float_as_uint(lo)), "r"(__float_as_uint(hi)));
    return r;
}
__device__ __forceinline__ void unpackf2(unsigned long long v, float& lo, float& hi){
    unsigned int a, b;
    asm("mov.b64 {%0, %1}, %2;" : "=r"(a), "=r"(b) : "l"(v));
    lo = __uint_as_float(a); hi = __uint_as_float(b);
}
__device__ __forceinline__ unsigned long long ffma2(
    unsigned long long a, unsigned long long b, unsigned long long c){
    unsigned long long d;
    asm("fma.rn.f32x2 %0, %1, %2, %3;" : "=l"(d) : "l"(a), "l"(b), "l"(c));
    return d;
}

// ---------------- plain SGEMM (encoder-Wi precompute only) ----------------
template<int BM,int BN,int BK,int TM,int TN>
__global__ void sgemm_k(const float* __restrict__ A, int lda,
                        const float* __restrict__ W,
                        const float* __restrict__ bias,
                        float* __restrict__ C,
                        int M, int N, int K)
{
    __shared__ float As[BK][BM+4];
    __shared__ float Ws[BK][BN+4];
    constexpr int NT = (BM/TM)*(BN/TN);
    const int tx = threadIdx.x;
    const int ty = threadIdx.y;
    const int tid = ty*(BN/TN)+tx;
    const int bm0 = blockIdx.y*BM;
    const int bn0 = blockIdx.x*BN;

    float acc[TM][TN];
    #pragma unroll
    for (int i=0;i<TM;i++)
        #pragma unroll
        for (int j=0;j<TN;j++) acc[i][j]=0.f;

    for (int k0=0;k0<K;k0+=BK){
        for (int i=tid;i<BM*BK;i+=NT){
            int kl=i%BK, ml=i/BK;
            int m=bm0+ml, kg=k0+kl;
            As[kl][ml] = (m<M && kg<K) ? A[(size_t)m*lda + kg] : 0.f;
        }
        for (int i=tid;i<BN*BK;i+=NT){
            int kl=i%BK, nl=i/BK;
            int n=bn0+nl, kg=k0+kl;
            Ws[kl][nl] = (n<N && kg<K) ? W[(size_t)n*K + kg] : 0.f;
        }
        __syncthreads();
        #pragma unroll
        for (int kk=0;kk<BK;kk++){
            float a[TM], b[TN];
            #pragma unroll
            for (int i=0;i<TM;i+=4){
                float4 v = *(const float4*)&As[kk][ty*TM+i];
                a[i]=v.x; a[i+1]=v.y; a[i+2]=v.z; a[i+3]=v.w;
            }
            #pragma unroll
            for (int j=0;j<TN;j+=4){
                float4 v = *(const float4*)&Ws[kk][tx*TN+j];
                b[j]=v.x; b[j+1]=v.y; b[j+2]=v.z; b[j+3]=v.w;
            }
            #pragma unroll
            for (int i=0;i<TM;i++)
                #pragma unroll
                for (int j=0;j<TN;j++)
                    acc[i][j] = fmaf(a[i], b[j], acc[i][j]);
        }
        __syncthreads();
    }
    #pragma unroll
    for (int i=0;i<TM;i++){
        int m=bm0+ty*TM+i;
        if (m>=M) continue;
        #pragma unroll
        for (int j=0;j<TN;j++){
            int n=bn0+tx*TN+j;
            if (n<N) C[(size_t)m*N+n] = __fadd_rn(acc[i][j], bias[n]);
        }
    }
}

// ============ fused GRU step kernels, fine-grained tiles ====================
// Tile: 32 hidden-j x 16 batch, all 3 gates in-block. grid (HH/32=16, BB/16=8)
// = 128 blocks, 256 threads: tx = j-pair (0..15), ty = b (0..15).
// Register-prefetch double buffering hides L2 latency behind FMA.

// encoder: gh GEMM (K=512) + gate + mask (gi precomputed)
__global__ __launch_bounds__(256) void gru_enc_f(
    const float* __restrict__ h_in, float* __restrict__ h_out,
    const float* __restrict__ Wh, const float* __restrict__ bh,
    const float* __restrict__ gi_t,
    const int* __restrict__ src_len, int t)
{
    __shared__ unsigned long long As2[32][17];
    __shared__ unsigned long long Ws2[3][32][17];
    const int tid = threadIdx.x;
    const int tx = tid & 15;
    const int ty = tid >> 4;
    const int j0 = blockIdx.x*32;
    const int b0 = blockIdx.y*16;

    // staging slot maps (fixed per thread)
    int w_off[6]; unsigned long long* w_tgt[6];
    #pragma unroll
    for (int s=0;s<6;s++){
        int i = tid + s*256;
        int kl = i & 31, r = i >> 5, jp = r & 15, g = r >> 4;
        w_off[s] = (g*HH + j0 + 2*jp)*HH + kl;
        w_tgt[s] = &Ws2[g][kl][jp];
    }
    int a_off[2]; unsigned long long* a_tgt[2];
    #pragma unroll
    for (int u=0;u<2;u++){
        int i = tid + u*256;
        a_off[u] = (b0 + (i>>5))*HH + (i&31);
        a_tgt[u] = &As2[i&31][i>>5];
    }

    unsigned long long ac0=0ull, ac1=0ull, ac2=0ull;
    float w0[6], w1[6], av[2];

    // preload tile 0
    #pragma unroll
    for (int s=0;s<6;s++){ w0[s]=Wh[w_off[s]]; w1[s]=Wh[w_off[s]+HH]; }
    #pragma unroll
    for (int u=0;u<2;u++) av[u]=h_in[a_off[u]];
    #pragma unroll
    for (int s=0;s<6;s++) *w_tgt[s] = packf2(w0[s], w1[s]);
    #pragma unroll
    for (int u=0;u<2;u++) *a_tgt[u] = packf2(av[u], av[u]);
    __syncthreads();

    for (int kt=0; kt<16; kt++){
        const int k1 = (kt+1)*32;
        if (kt<15){
            #pragma unroll
            for (int s=0;s<6;s++){ w0[s]=Wh[w_off[s]+k1]; w1[s]=Wh[w_off[s]+HH+k1]; }
            #pragma unroll
            for (int u=0;u<2;u++) av[u]=h_in[a_off[u]+k1];
        }
        #pragma unroll
        for (int kk=0;kk<32;kk++){
            unsigned long long a = As2[kk][ty];
            ac0 = ffma2(a, Ws2[0][kk][tx], ac0);
            ac1 = ffma2(a, Ws2[1][kk][tx], ac1);
            ac2 = ffma2(a, Ws2[2][kk][tx], ac2);
        }
        __syncthreads();
        if (kt<15){
            #pragma unroll
            for (int s=0;s<6;s++) *w_tgt[s] = packf2(w0[s], w1[s]);
            #pragma unroll
            for (int u=0;u<2;u++) *a_tgt[u] = packf2(av[u], av[u]);
            __syncthreads();
        }
    }

    // epilogue: gate for (b, j), (b, j+1)
    const int j = j0 + 2*tx;
    const int b = b0 + ty;
    const float* gi = gi_t + (size_t)b*G3H;
    float dr0,dr1,dz0,dz1,dn0,dn1;
    unpackf2(ac0, dr0,dr1);
    unpackf2(ac1, dz0,dz1);
    unpackf2(ac2, dn0,dn1);
    int frozen = (t >= src_len[b]);
    #pragma unroll
    for (int jj=0;jj<2;jj++){
        float gr = __fadd_rn(jj?dr1:dr0, bh[j+jj]);
        float gz = __fadd_rn(jj?dz1:dz0, bh[HH+j+jj]);
        float gn = __fadd_rn(jj?dn1:dn0, bh[2*HH+j+jj]);
        float r = xla_sigmoid(__fadd_rn(gi[j+jj],      gr));
        float z = xla_sigmoid(__fadd_rn(gi[HH+j+jj],   gz));
        float n = xla_tanh(__fadd_rn(gi[2*HH+j+jj], __fmul_rn(r, gn)));
        float hp = h_in[(size_t)b*HH + j+jj];
        float hn = __fadd_rn(__fmul_rn(__fsub_rn(1.f,z),n), __fmul_rn(z,hp));
        h_out[(size_t)b*HH + j+jj] = frozen ? hp : hn;
    }
}

// decoder: gi GEMM (K=257 incl rate tail) + gh GEMM (K=512) + gate
__global__ __launch_bounds__(256) void gru_dec_f(
    const float* __restrict__ h_in, float* __restrict__ h_out,
    const float* __restrict__ Wi, const float* __restrict__ bi,
    const float* __restrict__ Wh, const float* __restrict__ bh,
    const float* __restrict__ emb)
{
    __shared__ unsigned long long As2[32][17];
    __shared__ unsigned long long Ws2[3][32][17];
    __shared__ int   seid[16];
    __shared__ float srate[16];
    const int tid = threadIdx.x;
    const int tx = tid & 15;
    const int ty = tid >> 4;
    const int j0 = blockIdx.x*32;
    const int b0 = blockIdx.y*16;

    if (tid < 16){ seid[tid] = g_eid[b0+tid]; srate[tid] = g_rate[b0+tid]; }
    __syncthreads();

    // per-thread slot geometry
    int klv[6], jpv[6], gv[6];
    #pragma unroll
    for (int s=0;s<6;s++){
        int i = tid + s*256;
        klv[s] = i & 31; int r = i >> 5; jpv[s] = r & 15; gv[s] = r >> 4;
    }
    int akl[2], abl[2];
    #pragma unroll
    for (int u=0;u<2;u++){
        int i = tid + u*256;
        akl[u] = i & 31; abl[u] = i >> 5;
    }

    unsigned long long i0=0ull, i1=0ull, i2=0ull;
    unsigned long long h0=0ull, h1=0ull, h2=0ull;
    float w0[6], w1[6], av[2];

    // ---- phase 1: gi over emb[eid], K tiles 0..7 (k 0..255) ----
    {
        int wI_off[6], aI_off[2];
        #pragma unroll
        for (int s=0;s<6;s++)
            wI_off[s] = (gv[s]*HH + j0 + 2*jpv[s])*KX + klv[s];
        #pragma unroll
        for (int u=0;u<2;u++)
            aI_off[u] = seid[abl[u]]*EDIM + akl[u];

        #pragma unroll
        for (int s=0;s<6;s++){ w0[s]=Wi[wI_off[s]]; w1[s]=Wi[wI_off[s]+KX]; }
        #pragma unroll
        for (int u=0;u<2;u++) av[u]=emb[aI_off[u]];
        #pragma unroll
        for (int s=0;s<6;s++) Ws2[gv[s]][klv[s]][jpv[s]] = packf2(w0[s], w1[s]);
        #pragma unroll
        for (int u=0;u<2;u++) As2[akl[u]][abl[u]] = packf2(av[u], av[u]);
        __syncthreads();

        for (int kt=0; kt<8; kt++){
            const int k1 = (kt+1)*32;
            if (kt<7){
                #pragma unroll
                for (int s=0;s<6;s++){ w0[s]=Wi[wI_off[s]+k1]; w1[s]=Wi[wI_off[s]+KX+k1]; }
                #pragma unroll
                for (int u=0;u<2;u++) av[u]=emb[aI_off[u]+k1];
            }
            #pragma unroll
            for (int kk=0;kk<32;kk++){
                unsigned long long a = As2[kk][ty];
                i0 = ffma2(a, Ws2[0][kk][tx], i0);
                i1 = ffma2(a, Ws2[1][kk][tx], i1);
                i2 = ffma2(a, Ws2[2][kk][tx], i2);
            }
            __syncthreads();
            if (kt<7){
                #pragma unroll
                for (int s=0;s<6;s++) Ws2[gv[s]][klv[s]][jpv[s]] = packf2(w0[s], w1[s]);
                #pragma unroll
                for (int u=0;u<2;u++) As2[akl[u]][abl[u]] = packf2(av[u], av[u]);
                __syncthreads();
            }
        }
    }
    // rate tail: k = 256
    {
        const int j = j0 + 2*tx;
        float rv = srate[ty];
        unsigned long long rp = packf2(rv, rv);
        unsigned long long wt;
        wt = packf2(Wi[(0*HH + j)*KX + 256], Wi[(0*HH + j+1)*KX + 256]);
        i0 = ffma2(rp, wt, i0);
        wt = packf2(Wi[(1*HH + j)*KX + 256], Wi[(1*HH + j+1)*KX + 256]);
        i1 = ffma2(rp, wt, i1);
        wt = packf2(Wi[(2*HH + j)*KX + 256], Wi[(2*HH + j+1)*KX + 256]);
        i2 = ffma2(rp, wt, i2);
    }
    // ---- phase 2: gh over h, K tiles 0..15 ----
    {
        int wH_off[6], aH_off[2];
        #pragma unroll
        for (int s=0;s<6;s++)
            wH_off[s] = (gv[s]*HH + j0 + 2*jpv[s])*HH + klv[s];
        #pragma unroll
        for (int u=0;u<2;u++)
            aH_off[u] = (b0 + abl[u])*HH + akl[u];

        #pragma unroll
        for (int s=0;s<6;s++){ w0[s]=Wh[wH_off[s]]; w1[s]=Wh[wH_off[s]+HH]; }
        #pragma unroll
        for (int u=0;u<2;u++) av[u]=h_in[aH_off[u]];
        #pragma unroll
        for (int s=0;s<6;s++) Ws2[gv[s]][klv[s]][jpv[s]] = packf2(w0[s], w1[s]);
        #pragma unroll
        for (int u=0;u<2;u++) As2[akl[u]][abl[u]] = packf2(av[u], av[u]);
        __syncthreads();

        for (int kt=0; kt<16; kt++){
            const int k1 = (kt+1)*32;
            if (kt<15){
                #pragma unroll
                for (int s=0;s<6;s++){ w0[s]=Wh[wH_off[s]+k1]; w1[s]=Wh[wH_off[s]+HH+k1]; }
                #pragma unroll
                for (int u=0;u<2;u++) av[u]=h_in[aH_off[u]+k1];
            }
            #pragma unroll
            for (int kk=0;kk<32;kk++){
                unsigned long long a = As2[kk][ty];
                h0 = ffma2(a, Ws2[0][kk][tx], h0);
                h1 = ffma2(a, Ws2[1][kk][tx], h1);
                h2 = ffma2(a, Ws2[2][kk][tx], h2);
            }
            __syncthreads();
            if (kt<15){
                #pragma unroll
                for (int s=0;s<6;s++) Ws2[gv[s]][klv[s]][jpv[s]] = packf2(w0[s], w1[s]);
                #pragma unroll
                for (int u=0;u<2;u++) As2[akl[u]][abl[u]] = packf2(av[u], av[u]);
                __syncthreads();
            }
        }
    }

    // epilogue
    const int j = j0 + 2*tx;
    const int b = b0 + ty;
    float ir0,ir1,iz0,iz1,in0,in1, hr0,hr1,hz0,hz1,hn0,hn1;
    unpackf2(i0, ir0,ir1); unpackf2(i1, iz0,iz1); unpackf2(i2, in0,in1);
    unpackf2(h0, hr0,hr1); unpackf2(h1, hz0,hz1); unpackf2(h2, hn0,hn1);
    #pragma unroll
    for (int jj=0;jj<2;jj++){
        float giR = __fadd_rn(jj?ir1:ir0, bi[j+jj]);
        float giZ = __fadd_rn(jj?iz1:iz0, bi[HH+j+jj]);
        float giN = __fadd_rn(jj?in1:in0, bi[2*HH+j+jj]);
        float ghR = __fadd_rn(jj?hr1:hr0, bh[j+jj]);
        float ghZ = __fadd_rn(jj?hz1:hz0, bh[HH+j+jj]);
        float ghN = __fadd_rn(jj?hn1:hn0, bh[2*HH+j+jj]);
        float r = xla_sigmoid(__fadd_rn(giR, ghR));
        float z = xla_sigmoid(__fadd_rn(giZ, ghZ));
        float n = xla_tanh(__fadd_rn(giN, __fmul_rn(r, ghN)));
        float hp = h_in[(size_t)b*HH + j+jj];
        float hn = __fadd_rn(__fmul_rn(__fsub_rn(1.f,z),n), __fmul_rn(z,hp));
        h_out[(size_t)b*HH + j+jj] = hn;
    }
}

// ---------------- vocab GEMM: 128m x 64n tiles, 313 blocks, prefetch ------
__global__ __launch_bounds__(256) void vgemm_k(const float* __restrict__ A,
                                               const float* __restrict__ W,
                                               const float* __restrict__ bias,
                                               float* __restrict__ C)
{
    __shared__ float As[32][132];
    __shared__ float Ws[32][72];
    const int tid = threadIdx.x;
    const int tx = tid & 7;       // n-group: 8 n each
    const int ty = tid >> 3;      // m-group: 4 m each (0..31)
    const int bn0 = blockIdx.x*64;

    unsigned long long acc2[4][4];
    #pragma unroll
    for (int i=0;i<4;i++)
        #pragma unroll
        for (int p=0;p<4;p++) acc2[i][p]=0ull;

    float pa[16], pw[8];
    // preload tile 0
    #pragma unroll
    for (int s=0;s<16;s++){
        int i = tid + s*256;
        pa[s] = A[(i>>5)*HH + (i&31)];
    }
    #pragma unroll
    for (int s=0;s<8;s++){
        int i = tid + s*256;
        int n = bn0 + (i>>5);
        pw[s] = (n<VV) ? W[(size_t)n*HH + (i&31)] : 0.f;
    }
    #pragma unroll
    for (int s=0;s<16;s++){ int i = tid + s*256; As[i&31][i>>5] = pa[s]; }
    #pragma unroll
    for (int s=0;s<8;s++){  int i = tid + s*256; Ws[i&31][i>>5] = pw[s]; }
    __syncthreads();

    for (int kt=0; kt<16; kt++){
        const int k1 = (kt+1)*32;
        if (kt<15){
            #pragma unroll
            for (int s=0;s<16;s++){
                int i = tid + s*256;
                pa[s] = A[(i>>5)*HH + (i&31) + k1];
            }
            #pragma unroll
            for (int s=0;s<8;s++){
                int i = tid + s*256;
                int n = bn0 + (i>>5);
                pw[s] = (n<VV) ? W[(size_t)n*HH + (i&31) + k1] : 0.f;
            }
        }
        #pragma unroll
        for (int kk=0;kk<32;kk++){
            float4 a  = *(const float4*)&As[kk][ty*4];
            float4 b0 = *(const float4*)&Ws[kk][tx*8];
            float4 b1 = *(const float4*)&Ws[kk][tx*8+4];
            unsigned long long A2[4], B2[4];
            A2[0]=packf2(a.x,a.x); A2[1]=packf2(a.y,a.y);
            A2[2]=packf2(a.z,a.z); A2[3]=packf2(a.w,a.w);
            B2[0]=packf2(b0.x,b0.y); B2[1]=packf2(b0.z,b0.w);
            B2[2]=packf2(b1.x,b1.y); B2[3]=packf2(b1.z,b1.w);
            #pragma unroll
            for (int i=0;i<4;i++)
                #pragma unroll
                for (int p=0;p<4;p++)
                    acc2[i][p] = ffma2(A2[i], B2[p], acc2[i][p]);
        }
        __syncthreads();
        if (kt<15){
            #pragma unroll
            for (int s=0;s<16;s++){ int i = tid + s*256; As[i&31][i>>5] = pa[s]; }
            #pragma unroll
            for (int s=0;s<8;s++){  int i = tid + s*256; Ws[i&31][i>>5] = pw[s]; }
            __syncthreads();
        }
    }
    #pragma unroll
    for (int i=0;i<4;i++){
        int m = ty*4+i;
        #pragma unroll
        for (int p=0;p<4;p++){
            float lo, hi;
            unpackf2(acc2[i][p], lo, hi);
            int n0 = bn0 + tx*8 + p*2;
            if (n0   < VV) C[(size_t)m*VV + n0  ] = __fadd_rn(lo, bias[n0  ]);
            if (n0+1 < VV) C[(size_t)m*VV + n0+1] = __fadd_rn(hi, bias[n0+1]);
        }
    }
}

// ---------------- fused softmax (logp + argmax) + rate head ---------------
__global__ __launch_bounds__(256) void softrate_k(
    float* __restrict__ out, int step, const float* __restrict__ hcur,
    const float* __restrict__ emb,
    const float* __restrict__ W1, const float* __restrict__ b1,
    const float* __restrict__ W2, const float* __restrict__ b2)
{
    int b = blockIdx.x, tid = threadIdx.x;
    __shared__ float  sv[256];
    __shared__ int    si[256];
    __shared__ double sd[256];
    __shared__ float  xc[EDIM+HH];
    __shared__ double red[256];

    const float* row = g_logits + (size_t)b*VV;
    float m = -3.4e38f;
    for (int k=tid;k<VV;k+=256) m = fmaxf(m, row[k]);
    sv[tid]=m; __syncthreads();
    for (int s=128;s>0;s>>=1){ if (tid<s) sv[tid]=fmaxf(sv[tid],sv[tid+s]); __syncthreads(); }
    float mx = sv[0];
    __syncthreads();
    float ps=0.f; double pd=0.0; int cnt=0;
    for (int k=tid;k<VV;k+=256){
        ps += expf(__fsub_rn(row[k], mx));
        if (++cnt==16){ pd += (double)ps; ps=0.f; cnt=0; }
    }
    pd += (double)ps;
    sd[tid]=pd; __syncthreads();
    for (int st=128;st>0;st>>=1){ if (tid<st) sd[tid]+=sd[tid+st]; __syncthreads(); }
    float lsh = logf((float)sd[0]);
    float* o = out + ((size_t)step*BB + b)*VV;
    float bm = -3.4e38f; int bi_ = VV;
    for (int k=tid;k<VV;k+=256){
        float v = __fsub_rn(__fsub_rn(row[k], mx), lsh);
        o[k] = v;
        if (v>bm || (v==bm && k<bi_)){ bm=v; bi_=k; }
    }
    sv[tid]=bm; si[tid]=bi_; __syncthreads();
    for (int s=128;s>0;s>>=1){
        if (tid<s){
            float v2=sv[tid+s]; int i2=si[tid+s];
            if (v2>sv[tid] || (v2==sv[tid] && i2<si[tid])){ sv[tid]=v2; si[tid]=i2; }
        }
        __syncthreads();
    }
    int e = si[0];
    if (tid==0) g_eid[b] = e;
    __syncthreads();

    if (tid < EDIM) xc[tid] = emb[(size_t)e*EDIM + tid];
    for (int k=tid;k<HH;k+=256) xc[EDIM+k] = hcur[(size_t)b*HH + k];
    __syncthreads();
    double partial = 0.0;
    for (int j=tid;j<HH;j+=256){
        const float* w = W1 + (size_t)j*(EDIM+HH);
        float acc = 0.f;
        #pragma unroll 8
        for (int k=0;k<EDIM+HH;k+=4){
            float4 wv = *(const float4*)(w+k);
            acc = fmaf(wv.x, xc[k],   acc);
            acc = fmaf(wv.y, xc[k+1], acc);
            acc = fmaf(wv.z, xc[k+2], acc);
            acc = fmaf(wv.w, xc[k+3], acc);
        }
        float pre = __fadd_rn(acc, b1[j]);
        partial += (double)__fmul_rn(fmaxf(pre, 0.f), W2[j]);
    }
    red[tid]=partial; __syncthreads();
    for (int s=128;s>0;s>>=1){ if (tid<s) red[tid]+=red[tid+s]; __syncthreads(); }
    if (tid==0){
        float y = __fadd_rn((float)red[0], b2[0]);
        float pr = xla_sigmoid(y);
        out[(size_t)TTRG*BB*VV + step*BB + b] = pr;
        g_rate[b] = pr;
    }
}

// ---------------- init ----------------------------------------------------
__global__ void init_k(float* __restrict__ out, const int* __restrict__ trg_eid,
                       const float* __restrict__ trg_rate)
{
    long long i = (long long)blockIdx.x*blockDim.x + threadIdx.x;
    const long long RATE_OFF = (long long)TTRG*BB*VV;
    if (i < (long long)BB*VV) out[i] = 0.f;
    if (i < BB)               out[RATE_OFF + i] = 0.f;
    if (i < BB*HH)            g_h[i] = 0.f;
    if (i < BB){ g_eid[i] = trg_eid[i]; g_rate[i] = trg_rate[i]; }
}

// ---------------- launch ---------------------------------------------------
extern "C" void kernel_launch(void* const* d_in, const int* in_sizes, int n_in,
                              void* d_out, int out_size)
{
    const float* src      = (const float*)d_in[0];
    const int*   src_len  = (const int*)  d_in[1];
    const int*   trg_eid  = (const int*)  d_in[2];
    const float* trg_rate = (const float*)d_in[3];
    const float* emb      = (const float*)d_in[4];
    const float* enc_Wi   = (const float*)d_in[5];
    const float* enc_Wh   = (const float*)d_in[6];
    const float* enc_bi   = (const float*)d_in[7];
    const float* enc_bh   = (const float*)d_in[8];
    const float* dec_Wi   = (const float*)d_in[9];
    const float* dec_Wh   = (const float*)d_in[10];
    const float* dec_bi   = (const float*)d_in[11];
    const float* dec_bh   = (const float*)d_in[12];
    const float* We       = (const float*)d_in[13];
    const float* be       = (const float*)d_in[14];
    const float* W1       = (const float*)d_in[15];
    const float* b1       = (const float*)d_in[16];
    const float* W2       = (const float*)d_in[17];
    const float* b2       = (const float*)d_in[18];
    float* out = (float*)d_out;

    float *p_h, *p_h2, *p_gi_enc, *p_logits;
    cudaGetSymbolAddress((void**)&p_h,      g_h);
    cudaGetSymbolAddress((void**)&p_h2,     g_h2);
    cudaGetSymbolAddress((void**)&p_gi_enc, g_gi_enc);
    cudaGetSymbolAddress((void**)&p_logits, g_logits);

    float* hb[2] = {p_h, p_h2};
    int par = 0;

    init_k<<<10000,256>>>(out, trg_eid, trg_rate);

    sgemm_k<64,64,32,4,4><<<dim3(G3H/64, (TSRC*BB)/64), dim3(16,16)>>>(
        src, INDIM, enc_Wi, enc_bi, p_gi_enc, TSRC*BB, G3H, INDIM);

    for (int t=0;t<TSRC;t++){
        gru_enc_f<<<dim3(HH/32, BB/16), 256>>>(
            hb[par], hb[par^1], enc_Wh, enc_bh,
            p_gi_enc + (size_t)t*BB*G3H, src_len, t);
        par ^= 1;
    }

    for (int step=1; step<TTRG; step++){
        gru_dec_f<<<dim3(HH/32, BB/16), 256>>>(
            hb[par], hb[par^1], dec_Wi, dec_bi, dec_Wh, dec_bh, emb);
        par ^= 1;
        vgemm_k<<<(VV+63)/64, 256>>>(hb[par], We, be, p_logits);
        softrate_k<<<BB,256>>>(out, step, hb[par], emb, W1, b1, W2, b2);
    }
}

// round 12
// speedup vs baseline: 1.8803x; 1.0189x over previous
#include <cuda_runtime.h>
#include <math.h>

#define BB   128
#define HH   512
#define INDIM 256
#define EDIM 256
#define VV   20000
#define TSRC 64
#define TTRG 50
#define G3H  1536
#define KX   257

// ---------------- scratch (device globals; no allocation) ----------------
__device__ float g_h [BB*HH];
__device__ float g_h2[BB*HH];
__device__ float g_gi_enc[(size_t)TSRC*BB*G3H];
__device__ float g_logits[(size_t)BB*VV];
__device__ int   g_eid[BB];
__device__ float g_rate[BB];

// ---- XLA f32 tanh (rational approx) + logistic expansion, no FMA fusion --
__device__ __forceinline__ float xla_tanh(float x){
    float ax = fabsf(x);
    float xc = fmaxf(-7.90531110763549805f, fminf(7.90531110763549805f, x));
    float x2 = __fmul_rn(xc, xc);
    float np = -2.76076847742355e-16f;
    np = __fadd_rn(__fmul_rn(np, x2),  2.00018790482477e-13f);
    np = __fadd_rn(__fmul_rn(np, x2), -8.60467152213735e-11f);
    np = __fadd_rn(__fmul_rn(np, x2),  5.12229709037114e-08f);
    np = __fadd_rn(__fmul_rn(np, x2),  1.48572235717979e-05f);
    np = __fadd_rn(__fmul_rn(np, x2),  6.37261928875436e-04f);
    np = __fadd_rn(__fmul_rn(np, x2),  4.89352455891786e-03f);
    np = __fmul_rn(np, xc);
    float dp = 1.19825839466702e-06f;
    dp = __fadd_rn(__fmul_rn(dp, x2), 1.18534705686654e-04f);
    dp = __fadd_rn(__fmul_rn(dp, x2), 2.26843463243900e-03f);
    dp = __fadd_rn(__fmul_rn(dp, x2), 4.89352518554385e-03f);
    float r = __fdiv_rn(np, dp);
    return (ax < 0.0004f) ? x : r;
}
__device__ __forceinline__ float xla_sigmoid(float x){
    return __fadd_rn(0.5f, __fmul_rn(0.5f, xla_tanh(__fmul_rn(0.5f, x))));
}

// ---- packed f32x2 helpers --------------------------------------------------
__device__ __forceinline__ unsigned long long packf2(float lo, float hi){
    unsigned long long r;
    asm("mov.b64 %0, {%1, %2};" : "=l"(r)
        : "r"(__float_as_uint(lo)), "r"(__float_as_uint(hi)));
    return r;
}
__device__ __forceinline__ void unpackf2(unsigned long long v, float& lo, float& hi){
    unsigned int a, b;
    asm("mov.b64 {%0, %1}, %2;" : "=r"(a), "=r"(b) : "l"(v));
    lo = __uint_as_float(a); hi = __uint_as_float(b);
}
__device__ __forceinline__ unsigned long long ffma2(
    unsigned long long a, unsigned long long b, unsigned long long c){
    unsigned long long d;
    asm("fma.rn.f32x2 %0, %1, %2, %3;" : "=l"(d) : "l"(a), "l"(b), "l"(c));
    return d;
}

// ---------------- plain SGEMM (encoder-Wi precompute only) ----------------
template<int BM,int BN,int BK,int TM,int TN>
__global__ void sgemm_k(const float* __restrict__ A, int lda,
                        const float* __restrict__ W,
                        const float* __restrict__ bias,
                        float* __restrict__ C,
                        int M, int N, int K)
{
    __shared__ float As[BK][BM+4];
    __shared__ float Ws[BK][BN+4];
    constexpr int NT = (BM/TM)*(BN/TN);
    const int tx = threadIdx.x;
    const int ty = threadIdx.y;
    const int tid = ty*(BN/TN)+tx;
    const int bm0 = blockIdx.y*BM;
    const int bn0 = blockIdx.x*BN;

    float acc[TM][TN];
    #pragma unroll
    for (int i=0;i<TM;i++)
        #pragma unroll
        for (int j=0;j<TN;j++) acc[i][j]=0.f;

    for (int k0=0;k0<K;k0+=BK){
        for (int i=tid;i<BM*BK;i+=NT){
            int kl=i%BK, ml=i/BK;
            int m=bm0+ml, kg=k0+kl;
            As[kl][ml] = (m<M && kg<K) ? A[(size_t)m*lda + kg] : 0.f;
        }
        for (int i=tid;i<BN*BK;i+=NT){
            int kl=i%BK, nl=i/BK;
            int n=bn0+nl, kg=k0+kl;
            Ws[kl][nl] = (n<N && kg<K) ? W[(size_t)n*K + kg] : 0.f;
        }
        __syncthreads();
        #pragma unroll
        for (int kk=0;kk<BK;kk++){
            float a[TM], b[TN];
            #pragma unroll
            for (int i=0;i<TM;i+=4){
                float4 v = *(const float4*)&As[kk][ty*TM+i];
                a[i]=v.x; a[i+1]=v.y; a[i+2]=v.z; a[i+3]=v.w;
            }
            #pragma unroll
            for (int j=0;j<TN;j+=4){
                float4 v = *(const float4*)&Ws[kk][tx*TN+j];
                b[j]=v.x; b[j+1]=v.y; b[j+2]=v.z; b[j+3]=v.w;
            }
            #pragma unroll
            for (int i=0;i<TM;i++)
                #pragma unroll
                for (int j=0;j<TN;j++)
                    acc[i][j] = fmaf(a[i], b[j], acc[i][j]);
        }
        __syncthreads();
    }
    #pragma unroll
    for (int i=0;i<TM;i++){
        int m=bm0+ty*TM+i;
        if (m>=M) continue;
        #pragma unroll
        for (int j=0;j<TN;j++){
            int n=bn0+tx*TN+j;
            if (n<N) C[(size_t)m*N+n] = __fadd_rn(acc[i][j], bias[n]);
        }
    }
}

// ============ fused GRU step kernels ========================================
// Tile 32j x 16b, 256 threads, all 3 gates in-block. grid (16,8)=128.
// Ws staged as [g][jpair][kk] (pad 34) -> ulonglong2 loads over 2 k at once.

// encoder: gh GEMM (K=512) + gate + mask (gi precomputed)
__global__ __launch_bounds__(256) void gru_enc_f(
    const float* __restrict__ h_in, float* __restrict__ h_out,
    const float* __restrict__ Wh, const float* __restrict__ bh,
    const float* __restrict__ gi_t,
    const int* __restrict__ src_len, int t)
{
    __shared__ unsigned long long As2[32][17];
    __shared__ unsigned long long Wv[3][16][34];
    const int tid = threadIdx.x;
    const int tx = tid & 15;
    const int ty = tid >> 4;
    const int j0 = blockIdx.x*32;
    const int b0 = blockIdx.y*16;

    int w_off[6]; unsigned long long* w_tgt[6];
    #pragma unroll
    for (int s=0;s<6;s++){
        int i = tid + s*256;
        int kl = i & 31, r = i >> 5, jp = r & 15, g = r >> 4;
        w_off[s] = (g*HH + j0 + 2*jp)*HH + kl;
        w_tgt[s] = &Wv[g][jp][kl];
    }
    int a_off[2]; unsigned long long* a_tgt[2];
    #pragma unroll
    for (int u=0;u<2;u++){
        int i = tid + u*256;
        a_off[u] = (b0 + (i>>5))*HH + (i&31);
        a_tgt[u] = &As2[i&31][i>>5];
    }

    unsigned long long ac0=0ull, ac1=0ull, ac2=0ull;
    float w0[6], w1[6], av[2];

    #pragma unroll
    for (int s=0;s<6;s++){ w0[s]=Wh[w_off[s]]; w1[s]=Wh[w_off[s]+HH]; }
    #pragma unroll
    for (int u=0;u<2;u++) av[u]=h_in[a_off[u]];
    #pragma unroll
    for (int s=0;s<6;s++) *w_tgt[s] = packf2(w0[s], w1[s]);
    #pragma unroll
    for (int u=0;u<2;u++) *a_tgt[u] = packf2(av[u], av[u]);
    __syncthreads();

    for (int kt=0; kt<16; kt++){
        const int k1 = (kt+1)*32;
        if (kt<15){
            #pragma unroll
            for (int s=0;s<6;s++){ w0[s]=Wh[w_off[s]+k1]; w1[s]=Wh[w_off[s]+HH+k1]; }
            #pragma unroll
            for (int u=0;u<2;u++) av[u]=h_in[a_off[u]+k1];
        }
        #pragma unroll
        for (int kk=0;kk<32;kk+=2){
            ulonglong2 wr = *(const ulonglong2*)&Wv[0][tx][kk];
            ulonglong2 wz = *(const ulonglong2*)&Wv[1][tx][kk];
            ulonglong2 wn = *(const ulonglong2*)&Wv[2][tx][kk];
            unsigned long long a0 = As2[kk][ty];
            unsigned long long a1 = As2[kk+1][ty];
            ac0 = ffma2(a0, wr.x, ac0);
            ac1 = ffma2(a0, wz.x, ac1);
            ac2 = ffma2(a0, wn.x, ac2);
            ac0 = ffma2(a1, wr.y, ac0);
            ac1 = ffma2(a1, wz.y, ac1);
            ac2 = ffma2(a1, wn.y, ac2);
        }
        __syncthreads();
        if (kt<15){
            #pragma unroll
            for (int s=0;s<6;s++) *w_tgt[s] = packf2(w0[s], w1[s]);
            #pragma unroll
            for (int u=0;u<2;u++) *a_tgt[u] = packf2(av[u], av[u]);
            __syncthreads();
        }
    }

    const int j = j0 + 2*tx;
    const int b = b0 + ty;
    const float* gi = gi_t + (size_t)b*G3H;
    float dr0,dr1,dz0,dz1,dn0,dn1;
    unpackf2(ac0, dr0,dr1);
    unpackf2(ac1, dz0,dz1);
    unpackf2(ac2, dn0,dn1);
    int frozen = (t >= src_len[b]);
    #pragma unroll
    for (int jj=0;jj<2;jj++){
        float gr = __fadd_rn(jj?dr1:dr0, bh[j+jj]);
        float gz = __fadd_rn(jj?dz1:dz0, bh[HH+j+jj]);
        float gn = __fadd_rn(jj?dn1:dn0, bh[2*HH+j+jj]);
        float r = xla_sigmoid(__fadd_rn(gi[j+jj],      gr));
        float z = xla_sigmoid(__fadd_rn(gi[HH+j+jj],   gz));
        float n = xla_tanh(__fadd_rn(gi[2*HH+j+jj], __fmul_rn(r, gn)));
        float hp = h_in[(size_t)b*HH + j+jj];
        float hn = __fadd_rn(__fmul_rn(__fsub_rn(1.f,z),n), __fmul_rn(z,hp));
        h_out[(size_t)b*HH + j+jj] = frozen ? hp : hn;
    }
}

// decoder: gi GEMM (K=257 incl rate tail) + gh GEMM (K=512) + gate
__global__ __launch_bounds__(256) void gru_dec_f(
    const float* __restrict__ h_in, float* __restrict__ h_out,
    const float* __restrict__ Wi, const float* __restrict__ bi,
    const float* __restrict__ Wh, const float* __restrict__ bh,
    const float* __restrict__ emb)
{
    __shared__ unsigned long long As2[32][17];
    __shared__ unsigned long long Wv[3][16][34];
    __shared__ int   seid[16];
    __shared__ float srate[16];
    const int tid = threadIdx.x;
    const int tx = tid & 15;
    const int ty = tid >> 4;
    const int j0 = blockIdx.x*32;
    const int b0 = blockIdx.y*16;

    if (tid < 16){ seid[tid] = g_eid[b0+tid]; srate[tid] = g_rate[b0+tid]; }
    __syncthreads();

    int klv[6], jpv[6], gv[6];
    unsigned long long* w_tgt[6];
    #pragma unroll
    for (int s=0;s<6;s++){
        int i = tid + s*256;
        klv[s] = i & 31; int r = i >> 5; jpv[s] = r & 15; gv[s] = r >> 4;
        w_tgt[s] = &Wv[gv[s]][jpv[s]][klv[s]];
    }
    int akl[2], abl[2];
    #pragma unroll
    for (int u=0;u<2;u++){
        int i = tid + u*256;
        akl[u] = i & 31; abl[u] = i >> 5;
    }

    unsigned long long i0=0ull, i1=0ull, i2=0ull;
    unsigned long long h0=0ull, h1=0ull, h2=0ull;
    float w0[6], w1[6], av[2];

    // ---- phase 1: gi over emb[eid], k 0..255 ----
    {
        int wI_off[6], aI_off[2];
        #pragma unroll
        for (int s=0;s<6;s++)
            wI_off[s] = (gv[s]*HH + j0 + 2*jpv[s])*KX + klv[s];
        #pragma unroll
        for (int u=0;u<2;u++)
            aI_off[u] = seid[abl[u]]*EDIM + akl[u];

        #pragma unroll
        for (int s=0;s<6;s++){ w0[s]=Wi[wI_off[s]]; w1[s]=Wi[wI_off[s]+KX]; }
        #pragma unroll
        for (int u=0;u<2;u++) av[u]=emb[aI_off[u]];
        #pragma unroll
        for (int s=0;s<6;s++) *w_tgt[s] = packf2(w0[s], w1[s]);
        #pragma unroll
        for (int u=0;u<2;u++) As2[akl[u]][abl[u]] = packf2(av[u], av[u]);
        __syncthreads();

        for (int kt=0; kt<8; kt++){
            const int k1 = (kt+1)*32;
            if (kt<7){
                #pragma unroll
                for (int s=0;s<6;s++){ w0[s]=Wi[wI_off[s]+k1]; w1[s]=Wi[wI_off[s]+KX+k1]; }
                #pragma unroll
                for (int u=0;u<2;u++) av[u]=emb[aI_off[u]+k1];
            }
            #pragma unroll
            for (int kk=0;kk<32;kk+=2){
                ulonglong2 wr = *(const ulonglong2*)&Wv[0][tx][kk];
                ulonglong2 wz = *(const ulonglong2*)&Wv[1][tx][kk];
                ulonglong2 wn = *(const ulonglong2*)&Wv[2][tx][kk];
                unsigned long long a0 = As2[kk][ty];
                unsigned long long a1 = As2[kk+1][ty];
                i0 = ffma2(a0, wr.x, i0);
                i1 = ffma2(a0, wz.x, i1);
                i2 = ffma2(a0, wn.x, i2);
                i0 = ffma2(a1, wr.y, i0);
                i1 = ffma2(a1, wz.y, i1);
                i2 = ffma2(a1, wn.y, i2);
            }
            __syncthreads();
            if (kt<7){
                #pragma unroll
                for (int s=0;s<6;s++) *w_tgt[s] = packf2(w0[s], w1[s]);
                #pragma unroll
                for (int u=0;u<2;u++) As2[akl[u]][abl[u]] = packf2(av[u], av[u]);
                __syncthreads();
            }
        }
    }
    // rate tail: k = 256
    {
        const int j = j0 + 2*tx;
        float rv = srate[ty];
        unsigned long long rp = packf2(rv, rv);
        unsigned long long wt;
        wt = packf2(Wi[(0*HH + j)*KX + 256], Wi[(0*HH + j+1)*KX + 256]);
        i0 = ffma2(rp, wt, i0);
        wt = packf2(Wi[(1*HH + j)*KX + 256], Wi[(1*HH + j+1)*KX + 256]);
        i1 = ffma2(rp, wt, i1);
        wt = packf2(Wi[(2*HH + j)*KX + 256], Wi[(2*HH + j+1)*KX + 256]);
        i2 = ffma2(rp, wt, i2);
    }
    // ---- phase 2: gh over h, k 0..511 ----
    {
        int wH_off[6], aH_off[2];
        #pragma unroll
        for (int s=0;s<6;s++)
            wH_off[s] = (gv[s]*HH + j0 + 2*jpv[s])*HH + klv[s];
        #pragma unroll
        for (int u=0;u<2;u++)
            aH_off[u] = (b0 + abl[u])*HH + akl[u];

        #pragma unroll
        for (int s=0;s<6;s++){ w0[s]=Wh[wH_off[s]]; w1[s]=Wh[wH_off[s]+HH]; }
        #pragma unroll
        for (int u=0;u<2;u++) av[u]=h_in[aH_off[u]];
        #pragma unroll
        for (int s=0;s<6;s++) *w_tgt[s] = packf2(w0[s], w1[s]);
        #pragma unroll
        for (int u=0;u<2;u++) As2[akl[u]][abl[u]] = packf2(av[u], av[u]);
        __syncthreads();

        for (int kt=0; kt<16; kt++){
            const int k1 = (kt+1)*32;
            if (kt<15){
                #pragma unroll
                for (int s=0;s<6;s++){ w0[s]=Wh[wH_off[s]+k1]; w1[s]=Wh[wH_off[s]+HH+k1]; }
                #pragma unroll
                for (int u=0;u<2;u++) av[u]=h_in[aH_off[u]+k1];
            }
            #pragma unroll
            for (int kk=0;kk<32;kk+=2){
                ulonglong2 wr = *(const ulonglong2*)&Wv[0][tx][kk];
                ulonglong2 wz = *(const ulonglong2*)&Wv[1][tx][kk];
                ulonglong2 wn = *(const ulonglong2*)&Wv[2][tx][kk];
                unsigned long long a0 = As2[kk][ty];
                unsigned long long a1 = As2[kk+1][ty];
                h0 = ffma2(a0, wr.x, h0);
                h1 = ffma2(a0, wz.x, h1);
                h2 = ffma2(a0, wn.x, h2);
                h0 = ffma2(a1, wr.y, h0);
                h1 = ffma2(a1, wz.y, h1);
                h2 = ffma2(a1, wn.y, h2);
            }
            __syncthreads();
            if (kt<15){
                #pragma unroll
                for (int s=0;s<6;s++) *w_tgt[s] = packf2(w0[s], w1[s]);
                #pragma unroll
                for (int u=0;u<2;u++) As2[akl[u]][abl[u]] = packf2(av[u], av[u]);
                __syncthreads();
            }
        }
    }

    const int j = j0 + 2*tx;
    const int b = b0 + ty;
    float ir0,ir1,iz0,iz1,in0,in1, hr0,hr1,hz0,hz1,hn0,hn1;
    unpackf2(i0, ir0,ir1); unpackf2(i1, iz0,iz1); unpackf2(i2, in0,in1);
    unpackf2(h0, hr0,hr1); unpackf2(h1, hz0,hz1); unpackf2(h2, hn0,hn1);
    #pragma unroll
    for (int jj=0;jj<2;jj++){
        float giR = __fadd_rn(jj?ir1:ir0, bi[j+jj]);
        float giZ = __fadd_rn(jj?iz1:iz0, bi[HH+j+jj]);
        float giN = __fadd_rn(jj?in1:in0, bi[2*HH+j+jj]);
        float ghR = __fadd_rn(jj?hr1:hr0, bh[j+jj]);
        float ghZ = __fadd_rn(jj?hz1:hz0, bh[HH+j+jj]);
        float ghN = __fadd_rn(jj?hn1:hn0, bh[2*HH+j+jj]);
        float r = xla_sigmoid(__fadd_rn(giR, ghR));
        float z = xla_sigmoid(__fadd_rn(giZ, ghZ));
        float n = xla_tanh(__fadd_rn(giN, __fmul_rn(r, ghN)));
        float hp = h_in[(size_t)b*HH + j+jj];
        float hn = __fadd_rn(__fmul_rn(__fsub_rn(1.f,z),n), __fmul_rn(z,hp));
        h_out[(size_t)b*HH + j+jj] = hn;
    }
}

// ---------------- vocab GEMM v3: 128m x 64n, BK=16, >=3 blocks/SM ----------
__global__ __launch_bounds__(256,3) void vgemm_k(const float* __restrict__ A,
                                                 const float* __restrict__ W,
                                                 const float* __restrict__ bias,
                                                 float* __restrict__ C)
{
    __shared__ float As[16][132];
    __shared__ float Ws[16][72];
    const int tid = threadIdx.x;
    const int tx = tid & 7;       // 8 n each (4 pairs)
    const int ty = tid >> 3;      // 4 m each (0..31)
    const int bn0 = blockIdx.x*64;

    unsigned long long acc2[4][4];
    #pragma unroll
    for (int i=0;i<4;i++)
        #pragma unroll
        for (int p=0;p<4;p++) acc2[i][p]=0ull;

    float pa[8], pw[4];
    #pragma unroll
    for (int s=0;s<8;s++){
        int i = tid + s*256;
        pa[s] = A[(i>>4)*HH + (i&15)];
    }
    #pragma unroll
    for (int s=0;s<4;s++){
        int i = tid + s*256;
        int n = bn0 + (i>>4);
        pw[s] = (n<VV) ? W[(size_t)n*HH + (i&15)] : 0.f;
    }
    #pragma unroll
    for (int s=0;s<8;s++){ int i = tid + s*256; As[i&15][i>>4] = pa[s]; }
    #pragma unroll
    for (int s=0;s<4;s++){ int i = tid + s*256; Ws[i&15][i>>4] = pw[s]; }
    __syncthreads();

    for (int kt=0; kt<32; kt++){
        const int k1 = (kt+1)*16;
        if (kt<31){
            #pragma unroll
            for (int s=0;s<8;s++){
                int i = tid + s*256;
                pa[s] = A[(i>>4)*HH + (i&15) + k1];
            }
            #pragma unroll
            for (int s=0;s<4;s++){
                int i = tid + s*256;
                int n = bn0 + (i>>4);
                pw[s] = (n<VV) ? W[(size_t)n*HH + (i&15) + k1] : 0.f;
            }
        }
        #pragma unroll
        for (int kk=0;kk<16;kk++){
            float4 a  = *(const float4*)&As[kk][ty*4];
            float4 b0 = *(const float4*)&Ws[kk][tx*8];
            float4 b1 = *(const float4*)&Ws[kk][tx*8+4];
            unsigned long long A2[4], B2[4];
            A2[0]=packf2(a.x,a.x); A2[1]=packf2(a.y,a.y);
            A2[2]=packf2(a.z,a.z); A2[3]=packf2(a.w,a.w);
            B2[0]=packf2(b0.x,b0.y); B2[1]=packf2(b0.z,b0.w);
            B2[2]=packf2(b1.x,b1.y); B2[3]=packf2(b1.z,b1.w);
            #pragma unroll
            for (int i=0;i<4;i++)
                #pragma unroll
                for (int p=0;p<4;p++)
                    acc2[i][p] = ffma2(A2[i], B2[p], acc2[i][p]);
        }
        __syncthreads();
        if (kt<31){
            #pragma unroll
            for (int s=0;s<8;s++){ int i = tid + s*256; As[i&15][i>>4] = pa[s]; }
            #pragma unroll
            for (int s=0;s<4;s++){ int i = tid + s*256; Ws[i&15][i>>4] = pw[s]; }
            __syncthreads();
        }
    }
    #pragma unroll
    for (int i=0;i<4;i++){
        int m = ty*4+i;
        #pragma unroll
        for (int p=0;p<4;p++){
            float lo, hi;
            unpackf2(acc2[i][p], lo, hi);
            int n0 = bn0 + tx*8 + p*2;
            if (n0   < VV) C[(size_t)m*VV + n0  ] = __fadd_rn(lo, bias[n0  ]);
            if (n0+1 < VV) C[(size_t)m*VV + n0+1] = __fadd_rn(hi, bias[n0+1]);
        }
    }
}

// ---------------- fused softmax (logp + argmax) + rate head ---------------
__global__ __launch_bounds__(256) void softrate_k(
    float* __restrict__ out, int step, const float* __restrict__ hcur,
    const float* __restrict__ emb,
    const float* __restrict__ W1, const float* __restrict__ b1,
    const float* __restrict__ W2, const float* __restrict__ b2)
{
    int b = blockIdx.x, tid = threadIdx.x;
    __shared__ float  sv[256];
    __shared__ int    si[256];
    __shared__ double sd[256];
    __shared__ float  xc[EDIM+HH];
    __shared__ double red[256];

    const float* row = g_logits + (size_t)b*VV;
    float m = -3.4e38f;
    for (int k=tid;k<VV;k+=256) m = fmaxf(m, row[k]);
    sv[tid]=m; __syncthreads();
    for (int s=128;s>0;s>>=1){ if (tid<s) sv[tid]=fmaxf(sv[tid],sv[tid+s]); __syncthreads(); }
    float mx = sv[0];
    __syncthreads();
    float ps=0.f; double pd=0.0; int cnt=0;
    for (int k=tid;k<VV;k+=256){
        ps += expf(__fsub_rn(row[k], mx));
        if (++cnt==16){ pd += (double)ps; ps=0.f; cnt=0; }
    }
    pd += (double)ps;
    sd[tid]=pd; __syncthreads();
    for (int st=128;st>0;st>>=1){ if (tid<st) sd[tid]+=sd[tid+st]; __syncthreads(); }
    float lsh = logf((float)sd[0]);
    float* o = out + ((size_t)step*BB + b)*VV;
    float bm = -3.4e38f; int bi_ = VV;
    for (int k=tid;k<VV;k+=256){
        float v = __fsub_rn(__fsub_rn(row[k], mx), lsh);
        o[k] = v;
        if (v>bm || (v==bm && k<bi_)){ bm=v; bi_=k; }
    }
    sv[tid]=bm; si[tid]=bi_; __syncthreads();
    for (int s=128;s>0;s>>=1){
        if (tid<s){
            float v2=sv[tid+s]; int i2=si[tid+s];
            if (v2>sv[tid] || (v2==sv[tid] && i2<si[tid])){ sv[tid]=v2; si[tid]=i2; }
        }
        __syncthreads();
    }
    int e = si[0];
    if (tid==0) g_eid[b] = e;
    __syncthreads();

    if (tid < EDIM) xc[tid] = emb[(size_t)e*EDIM + tid];
    for (int k=tid;k<HH;k+=256) xc[EDIM+k] = hcur[(size_t)b*HH + k];
    __syncthreads();
    double partial = 0.0;
    for (int j=tid;j<HH;j+=256){
        const float* w = W1 + (size_t)j*(EDIM+HH);
        float acc = 0.f;
        #pragma unroll 8
        for (int k=0;k<EDIM+HH;k+=4){
            float4 wv = *(const float4*)(w+k);
            acc = fmaf(wv.x, xc[k],   acc);
            acc = fmaf(wv.y, xc[k+1], acc);
            acc = fmaf(wv.z, xc[k+2], acc);
            acc = fmaf(wv.w, xc[k+3], acc);
        }
        float pre = __fadd_rn(acc, b1[j]);
        partial += (double)__fmul_rn(fmaxf(pre, 0.f), W2[j]);
    }
    red[tid]=partial; __syncthreads();
    for (int s=128;s>0;s>>=1){ if (tid<s) red[tid]+=red[tid+s]; __syncthreads(); }
    if (tid==0){
        float y = __fadd_rn((float)red[0], b2[0]);
        float pr = xla_sigmoid(y);
        out[(size_t)TTRG*BB*VV + step*BB + b] = pr;
        g_rate[b] = pr;
    }
}

// ---------------- init ----------------------------------------------------
__global__ void init_k(float* __restrict__ out, const int* __restrict__ trg_eid,
                       const float* __restrict__ trg_rate)
{
    long long i = (long long)blockIdx.x*blockDim.x + threadIdx.x;
    const long long RATE_OFF = (long long)TTRG*BB*VV;
    if (i < (long long)BB*VV) out[i] = 0.f;
    if (i < BB)               out[RATE_OFF + i] = 0.f;
    if (i < BB*HH)            g_h[i] = 0.f;
    if (i < BB){ g_eid[i] = trg_eid[i]; g_rate[i] = trg_rate[i]; }
}

// ---------------- launch ---------------------------------------------------
extern "C" void kernel_launch(void* const* d_in, const int* in_sizes, int n_in,
                              void* d_out, int out_size)
{
    const float* src      = (const float*)d_in[0];
    const int*   src_len  = (const int*)  d_in[1];
    const int*   trg_eid  = (const int*)  d_in[2];
    const float* trg_rate = (const float*)d_in[3];
    const float* emb      = (const float*)d_in[4];
    const float* enc_Wi   = (const float*)d_in[5];
    const float* enc_Wh   = (const float*)d_in[6];
    const float* enc_bi   = (const float*)d_in[7];
    const float* enc_bh   = (const float*)d_in[8];
    const float* dec_Wi   = (const float*)d_in[9];
    const float* dec_Wh   = (const float*)d_in[10];
    const float* dec_bi   = (const float*)d_in[11];
    const float* dec_bh   = (const float*)d_in[12];
    const float* We       = (const float*)d_in[13];
    const float* be       = (const float*)d_in[14];
    const float* W1       = (const float*)d_in[15];
    const float* b1       = (const float*)d_in[16];
    const float* W2       = (const float*)d_in[17];
    const float* b2       = (const float*)d_in[18];
    float* out = (float*)d_out;

    float *p_h, *p_h2, *p_gi_enc, *p_logits;
    cudaGetSymbolAddress((void**)&p_h,      g_h);
    cudaGetSymbolAddress((void**)&p_h2,     g_h2);
    cudaGetSymbolAddress((void**)&p_gi_enc, g_gi_enc);
    cudaGetSymbolAddress((void**)&p_logits, g_logits);

    float* hb[2] = {p_h, p_h2};
    int par = 0;

    init_k<<<10000,256>>>(out, trg_eid, trg_rate);

    sgemm_k<64,64,32,4,4><<<dim3(G3H/64, (TSRC*BB)/64), dim3(16,16)>>>(
        src, INDIM, enc_Wi, enc_bi, p_gi_enc, TSRC*BB, G3H, INDIM);

    for (int t=0;t<TSRC;t++){
        gru_enc_f<<<dim3(HH/32, BB/16), 256>>>(
            hb[par], hb[par^1], enc_Wh, enc_bh,
            p_gi_enc + (size_t)t*BB*G3H, src_len, t);
        par ^= 1;
    }

    for (int step=1; step<TTRG; step++){
        gru_dec_f<<<dim3(HH/32, BB/16), 256>>>(
            hb[par], hb[par^1], dec_Wi, dec_bi, dec_Wh, dec_bh, emb);
        par ^= 1;
        vgemm_k<<<(VV+63)/64, 256>>>(hb[par], We, be, p_logits);
        softrate_k<<<BB,256>>>(out, step, hb[par], emb, W1, b1, W2, b2);
    }
}

// round 14
// speedup vs baseline: 2.1102x; 1.1223x over previous
#include <cuda_runtime.h>
#include <cuda_bf16.h>
#include <math.h>

#define BB   128
#define HH   512
#define INDIM 256
#define EDIM 256
#define VV   20000
#define TSRC 64
#define TTRG 50
#define G3H  1536
#define KX   257
#define NT2  157            // ceil(VV/128)
#define NPAD (NT2*128)      // 20096

// ---------------- scratch (device globals; no allocation) ----------------
__device__ float g_h [BB*HH];
__device__ float g_h2[BB*HH];
__device__ float g_gi_enc[(size_t)TSRC*BB*G3H];
__device__ float g_logits[(size_t)BB*VV];
__device__ int   g_eid[BB];
__device__ float g_rate[BB];
__device__ __align__(16) __nv_bfloat16 g_hb[3*BB*HH];              // h planes
__device__ __align__(16) __nv_bfloat16 g_wb[(size_t)3*NPAD*HH];    // We planes

__constant__ int c_PI[6] = {0,0,1,1,0,2};
__constant__ int c_PJ[6] = {0,1,0,1,2,0};

// ---- XLA f32 tanh (rational approx) + logistic expansion, no FMA fusion --
__device__ __forceinline__ float xla_tanh(float x){
    float ax = fabsf(x);
    float xc = fmaxf(-7.90531110763549805f, fminf(7.90531110763549805f, x));
    float x2 = __fmul_rn(xc, xc);
    float np = -2.76076847742355e-16f;
    np = __fadd_rn(__fmul_rn(np, x2),  2.00018790482477e-13f);
    np = __fadd_rn(__fmul_rn(np, x2), -8.60467152213735e-11f);
    np = __fadd_rn(__fmul_rn(np, x2),  5.12229709037114e-08f);
    np = __fadd_rn(__fmul_rn(np, x2),  1.48572235717979e-05f);
    np = __fadd_rn(__fmul_rn(np, x2),  6.37261928875436e-04f);
    np = __fadd_rn(__fmul_rn(np, x2),  4.89352455891786e-03f);
    np = __fmul_rn(np, xc);
    float dp = 1.19825839466702e-06f;
    dp = __fadd_rn(__fmul_rn(dp, x2), 1.18534705686654e-04f);
    dp = __fadd_rn(__fmul_rn(dp, x2), 2.26843463243900e-03f);
    dp = __fadd_rn(__fmul_rn(dp, x2), 4.89352518554385e-03f);
    float r = __fdiv_rn(np, dp);
    return (ax < 0.0004f) ? x : r;
}
__device__ __forceinline__ float xla_sigmoid(float x){
    return __fadd_rn(0.5f, __fmul_rn(0.5f, xla_tanh(__fmul_rn(0.5f, x))));
}

// ---- packed f32x2 helpers --------------------------------------------------
__device__ __forceinline__ unsigned long long packf2(float lo, float hi){
    unsigned long long r;
    asm("mov.b64 %0, {%1, %2};" : "=l"(r)
        : "r"(__float_as_uint(lo)), "r"(__float_as_uint(hi)));
    return r;
}
__device__ __forceinline__ void unpackf2(unsigned long long v, float& lo, float& hi){
    unsigned int a, b;
    asm("mov.b64 {%0, %1}, %2;" : "=r"(a), "=r"(b) : "l"(v));
    lo = __uint_as_float(a); hi = __uint_as_float(b);
}
__device__ __forceinline__ unsigned long long ffma2(
    unsigned long long a, unsigned long long b, unsigned long long c){
    unsigned long long d;
    asm("fma.rn.f32x2 %0, %1, %2, %3;" : "=l"(d) : "l"(a), "l"(b), "l"(c));
    return d;
}

// ---- mma / ldmatrix / cp.async helpers (base-target features) -------------
__device__ __forceinline__ unsigned smem_u32(const void* p){
    unsigned a;
    asm("{ .reg .u64 t; cvta.to.shared.u64 t, %1; cvt.u32.u64 %0, t; }"
        : "=r"(a) : "l"(p));
    return a;
}
__device__ __forceinline__ void ldsm_x4(unsigned&r0,unsigned&r1,unsigned&r2,unsigned&r3,
                                        unsigned addr){
    asm volatile("ldmatrix.sync.aligned.m8n8.x4.shared.b16 {%0,%1,%2,%3}, [%4];"
        : "=r"(r0),"=r"(r1),"=r"(r2),"=r"(r3) : "r"(addr));
}
__device__ __forceinline__ void ldsm_x2(unsigned&r0,unsigned&r1, unsigned addr){
    asm volatile("ldmatrix.sync.aligned.m8n8.x2.shared.b16 {%0,%1}, [%2];"
        : "=r"(r0),"=r"(r1) : "r"(addr));
}
__device__ __forceinline__ void mma16816(float* d, unsigned a0,unsigned a1,
                                         unsigned a2,unsigned a3,
                                         unsigned b0,unsigned b1){
    asm volatile("mma.sync.aligned.m16n8k16.row.col.f32.bf16.bf16.f32 "
        "{%0,%1,%2,%3}, {%4,%5,%6,%7}, {%8,%9}, {%0,%1,%2,%3};"
        : "+f"(d[0]),"+f"(d[1]),"+f"(d[2]),"+f"(d[3])
        : "r"(a0),"r"(a1),"r"(a2),"r"(a3),"r"(b0),"r"(b1));
}
__device__ __forceinline__ void cpasync16(unsigned saddr, const void* g){
    asm volatile("cp.async.cg.shared.global [%0], [%1], 16;" :: "r"(saddr), "l"(g));
}
#define CP_COMMIT() asm volatile("cp.async.commit_group;")
#define CP_WAIT1()  asm volatile("cp.async.wait_group 1;")
#define CP_WAIT0()  asm volatile("cp.async.wait_group 0;")

// ---------------- plain SGEMM (encoder-Wi precompute only) ----------------
template<int BM,int BN,int BK,int TM,int TN>
__global__ void sgemm_k(const float* __restrict__ A, int lda,
                        const float* __restrict__ W,
                        const float* __restrict__ bias,
                        float* __restrict__ C,
                        int M, int N, int K)
{
    __shared__ float As[BK][BM+4];
    __shared__ float Ws[BK][BN+4];
    constexpr int NT = (BM/TM)*(BN/TN);
    const int tx = threadIdx.x;
    const int ty = threadIdx.y;
    const int tid = ty*(BN/TN)+tx;
    const int bm0 = blockIdx.y*BM;
    const int bn0 = blockIdx.x*BN;

    float acc[TM][TN];
    #pragma unroll
    for (int i=0;i<TM;i++)
        #pragma unroll
        for (int j=0;j<TN;j++) acc[i][j]=0.f;

    for (int k0=0;k0<K;k0+=BK){
        for (int i=tid;i<BM*BK;i+=NT){
            int kl=i%BK, ml=i/BK;
            int m=bm0+ml, kg=k0+kl;
            As[kl][ml] = (m<M && kg<K) ? A[(size_t)m*lda + kg] : 0.f;
        }
        for (int i=tid;i<BN*BK;i+=NT){
            int kl=i%BK, nl=i/BK;
            int n=bn0+nl, kg=k0+kl;
            Ws[kl][nl] = (n<N && kg<K) ? W[(size_t)n*K + kg] : 0.f;
        }
        __syncthreads();
        #pragma unroll
        for (int kk=0;kk<BK;kk++){
            float a[TM], b[TN];
            #pragma unroll
            for (int i=0;i<TM;i+=4){
                float4 v = *(const float4*)&As[kk][ty*TM+i];
                a[i]=v.x; a[i+1]=v.y; a[i+2]=v.z; a[i+3]=v.w;
            }
            #pragma unroll
            for (int j=0;j<TN;j+=4){
                float4 v = *(const float4*)&Ws[kk][tx*TN+j];
                b[j]=v.x; b[j+1]=v.y; b[j+2]=v.z; b[j+3]=v.w;
            }
            #pragma unroll
            for (int i=0;i<TM;i++)
                #pragma unroll
                for (int j=0;j<TN;j++)
                    acc[i][j] = fmaf(a[i], b[j], acc[i][j]);
        }
        __syncthreads();
    }
    #pragma unroll
    for (int i=0;i<TM;i++){
        int m=bm0+ty*TM+i;
        if (m>=M) continue;
        #pragma unroll
        for (int j=0;j<TN;j++){
            int n=bn0+tx*TN+j;
            if (n<N) C[(size_t)m*N+n] = __fadd_rn(acc[i][j], bias[n]);
        }
    }
}

// ============ fused GRU step kernels (R12, bit-identical) ==================
__global__ __launch_bounds__(256) void gru_enc_f(
    const float* __restrict__ h_in, float* __restrict__ h_out,
    const float* __restrict__ Wh, const float* __restrict__ bh,
    const float* __restrict__ gi_t,
    const int* __restrict__ src_len, int t)
{
    __shared__ unsigned long long As2[32][17];
    __shared__ unsigned long long Wv[3][16][34];
    const int tid = threadIdx.x;
    const int tx = tid & 15;
    const int ty = tid >> 4;
    const int j0 = blockIdx.x*32;
    const int b0 = blockIdx.y*16;

    int w_off[6]; unsigned long long* w_tgt[6];
    #pragma unroll
    for (int s=0;s<6;s++){
        int i = tid + s*256;
        int kl = i & 31, r = i >> 5, jp = r & 15, g = r >> 4;
        w_off[s] = (g*HH + j0 + 2*jp)*HH + kl;
        w_tgt[s] = &Wv[g][jp][kl];
    }
    int a_off[2]; unsigned long long* a_tgt[2];
    #pragma unroll
    for (int u=0;u<2;u++){
        int i = tid + u*256;
        a_off[u] = (b0 + (i>>5))*HH + (i&31);
        a_tgt[u] = &As2[i&31][i>>5];
    }

    unsigned long long ac0=0ull, ac1=0ull, ac2=0ull;
    float w0[6], w1[6], av[2];

    #pragma unroll
    for (int s=0;s<6;s++){ w0[s]=Wh[w_off[s]]; w1[s]=Wh[w_off[s]+HH]; }
    #pragma unroll
    for (int u=0;u<2;u++) av[u]=h_in[a_off[u]];
    #pragma unroll
    for (int s=0;s<6;s++) *w_tgt[s] = packf2(w0[s], w1[s]);
    #pragma unroll
    for (int u=0;u<2;u++) *a_tgt[u] = packf2(av[u], av[u]);
    __syncthreads();

    for (int kt=0; kt<16; kt++){
        const int k1 = (kt+1)*32;
        if (kt<15){
            #pragma unroll
            for (int s=0;s<6;s++){ w0[s]=Wh[w_off[s]+k1]; w1[s]=Wh[w_off[s]+HH+k1]; }
            #pragma unroll
            for (int u=0;u<2;u++) av[u]=h_in[a_off[u]+k1];
        }
        #pragma unroll
        for (int kk=0;kk<32;kk+=2){
            ulonglong2 wr = *(const ulonglong2*)&Wv[0][tx][kk];
            ulonglong2 wz = *(const ulonglong2*)&Wv[1][tx][kk];
            ulonglong2 wn = *(const ulonglong2*)&Wv[2][tx][kk];
            unsigned long long a0 = As2[kk][ty];
            unsigned long long a1 = As2[kk+1][ty];
            ac0 = ffma2(a0, wr.x, ac0);
            ac1 = ffma2(a0, wz.x, ac1);
            ac2 = ffma2(a0, wn.x, ac2);
            ac0 = ffma2(a1, wr.y, ac0);
            ac1 = ffma2(a1, wz.y, ac1);
            ac2 = ffma2(a1, wn.y, ac2);
        }
        __syncthreads();
        if (kt<15){
            #pragma unroll
            for (int s=0;s<6;s++) *w_tgt[s] = packf2(w0[s], w1[s]);
            #pragma unroll
            for (int u=0;u<2;u++) *a_tgt[u] = packf2(av[u], av[u]);
            __syncthreads();
        }
    }

    const int j = j0 + 2*tx;
    const int b = b0 + ty;
    const float* gi = gi_t + (size_t)b*G3H;
    float dr0,dr1,dz0,dz1,dn0,dn1;
    unpackf2(ac0, dr0,dr1);
    unpackf2(ac1, dz0,dz1);
    unpackf2(ac2, dn0,dn1);
    int frozen = (t >= src_len[b]);
    #pragma unroll
    for (int jj=0;jj<2;jj++){
        float gr = __fadd_rn(jj?dr1:dr0, bh[j+jj]);
        float gz = __fadd_rn(jj?dz1:dz0, bh[HH+j+jj]);
        float gn = __fadd_rn(jj?dn1:dn0, bh[2*HH+j+jj]);
        float r = xla_sigmoid(__fadd_rn(gi[j+jj],      gr));
        float z = xla_sigmoid(__fadd_rn(gi[HH+j+jj],   gz));
        float n = xla_tanh(__fadd_rn(gi[2*HH+j+jj], __fmul_rn(r, gn)));
        float hp = h_in[(size_t)b*HH + j+jj];
        float hn = __fadd_rn(__fmul_rn(__fsub_rn(1.f,z),n), __fmul_rn(z,hp));
        h_out[(size_t)b*HH + j+jj] = frozen ? hp : hn;
    }
}

__global__ __launch_bounds__(256) void gru_dec_f(
    const float* __restrict__ h_in, float* __restrict__ h_out,
    const float* __restrict__ Wi, const float* __restrict__ bi,
    const float* __restrict__ Wh, const float* __restrict__ bh,
    const float* __restrict__ emb)
{
    __shared__ unsigned long long As2[32][17];
    __shared__ unsigned long long Wv[3][16][34];
    __shared__ int   seid[16];
    __shared__ float srate[16];
    const int tid = threadIdx.x;
    const int tx = tid & 15;
    const int ty = tid >> 4;
    const int j0 = blockIdx.x*32;
    const int b0 = blockIdx.y*16;

    if (tid < 16){ seid[tid] = g_eid[b0+tid]; srate[tid] = g_rate[b0+tid]; }
    __syncthreads();

    int klv[6], jpv[6], gv[6];
    unsigned long long* w_tgt[6];
    #pragma unroll
    for (int s=0;s<6;s++){
        int i = tid + s*256;
        klv[s] = i & 31; int r = i >> 5; jpv[s] = r & 15; gv[s] = r >> 4;
        w_tgt[s] = &Wv[gv[s]][jpv[s]][klv[s]];
    }
    int akl[2], abl[2];
    #pragma unroll
    for (int u=0;u<2;u++){
        int i = tid + u*256;
        akl[u] = i & 31; abl[u] = i >> 5;
    }

    unsigned long long i0=0ull, i1=0ull, i2=0ull;
    unsigned long long h0=0ull, h1=0ull, h2=0ull;
    float w0[6], w1[6], av[2];

    {
        int wI_off[6], aI_off[2];
        #pragma unroll
        for (int s=0;s<6;s++)
            wI_off[s] = (gv[s]*HH + j0 + 2*jpv[s])*KX + klv[s];
        #pragma unroll
        for (int u=0;u<2;u++)
            aI_off[u] = seid[abl[u]]*EDIM + akl[u];

        #pragma unroll
        for (int s=0;s<6;s++){ w0[s]=Wi[wI_off[s]]; w1[s]=Wi[wI_off[s]+KX]; }
        #pragma unroll
        for (int u=0;u<2;u++) av[u]=emb[aI_off[u]];
        #pragma unroll
        for (int s=0;s<6;s++) *w_tgt[s] = packf2(w0[s], w1[s]);
        #pragma unroll
        for (int u=0;u<2;u++) As2[akl[u]][abl[u]] = packf2(av[u], av[u]);
        __syncthreads();

        for (int kt=0; kt<8; kt++){
            const int k1 = (kt+1)*32;
            if (kt<7){
                #pragma unroll
                for (int s=0;s<6;s++){ w0[s]=Wi[wI_off[s]+k1]; w1[s]=Wi[wI_off[s]+KX+k1]; }
                #pragma unroll
                for (int u=0;u<2;u++) av[u]=emb[aI_off[u]+k1];
            }
            #pragma unroll
            for (int kk=0;kk<32;kk+=2){
                ulonglong2 wr = *(const ulonglong2*)&Wv[0][tx][kk];
                ulonglong2 wz = *(const ulonglong2*)&Wv[1][tx][kk];
                ulonglong2 wn = *(const ulonglong2*)&Wv[2][tx][kk];
                unsigned long long a0 = As2[kk][ty];
                unsigned long long a1 = As2[kk+1][ty];
                i0 = ffma2(a0, wr.x, i0);
                i1 = ffma2(a0, wz.x, i1);
                i2 = ffma2(a0, wn.x, i2);
                i0 = ffma2(a1, wr.y, i0);
                i1 = ffma2(a1, wz.y, i1);
                i2 = ffma2(a1, wn.y, i2);
            }
            __syncthreads();
            if (kt<7){
                #pragma unroll
                for (int s=0;s<6;s++) *w_tgt[s] = packf2(w0[s], w1[s]);
                #pragma unroll
                for (int u=0;u<2;u++) As2[akl[u]][abl[u]] = packf2(av[u], av[u]);
                __syncthreads();
            }
        }
    }
    {
        const int j = j0 + 2*tx;
        float rv = srate[ty];
        unsigned long long rp = packf2(rv, rv);
        unsigned long long wt;
        wt = packf2(Wi[(0*HH + j)*KX + 256], Wi[(0*HH + j+1)*KX + 256]);
        i0 = ffma2(rp, wt, i0);
        wt = packf2(Wi[(1*HH + j)*KX + 256], Wi[(1*HH + j+1)*KX + 256]);
        i1 = ffma2(rp, wt, i1);
        wt = packf2(Wi[(2*HH + j)*KX + 256], Wi[(2*HH + j+1)*KX + 256]);
        i2 = ffma2(rp, wt, i2);
    }
    {
        int wH_off[6], aH_off[2];
        #pragma unroll
        for (int s=0;s<6;s++)
            wH_off[s] = (gv[s]*HH + j0 + 2*jpv[s])*HH + klv[s];
        #pragma unroll
        for (int u=0;u<2;u++)
            aH_off[u] = (b0 + abl[u])*HH + akl[u];

        #pragma unroll
        for (int s=0;s<6;s++){ w0[s]=Wh[wH_off[s]]; w1[s]=Wh[wH_off[s]+HH]; }
        #pragma unroll
        for (int u=0;u<2;u++) av[u]=h_in[aH_off[u]];
        #pragma unroll
        for (int s=0;s<6;s++) *w_tgt[s] = packf2(w0[s], w1[s]);
        #pragma unroll
        for (int u=0;u<2;u++) As2[akl[u]][abl[u]] = packf2(av[u], av[u]);
        __syncthreads();

        for (int kt=0; kt<16; kt++){
            const int k1 = (kt+1)*32;
            if (kt<15){
                #pragma unroll
                for (int s=0;s<6;s++){ w0[s]=Wh[wH_off[s]+k1]; w1[s]=Wh[wH_off[s]+HH+k1]; }
                #pragma unroll
                for (int u=0;u<2;u++) av[u]=h_in[aH_off[u]+k1];
            }
            #pragma unroll
            for (int kk=0;kk<32;kk+=2){
                ulonglong2 wr = *(const ulonglong2*)&Wv[0][tx][kk];
                ulonglong2 wz = *(const ulonglong2*)&Wv[1][tx][kk];
                ulonglong2 wn = *(const ulonglong2*)&Wv[2][tx][kk];
                unsigned long long a0 = As2[kk][ty];
                unsigned long long a1 = As2[kk+1][ty];
                h0 = ffma2(a0, wr.x, h0);
                h1 = ffma2(a0, wz.x, h1);
                h2 = ffma2(a0, wn.x, h2);
                h0 = ffma2(a1, wr.y, h0);
                h1 = ffma2(a1, wz.y, h1);
                h2 = ffma2(a1, wn.y, h2);
            }
            __syncthreads();
            if (kt<15){
                #pragma unroll
                for (int s=0;s<6;s++) *w_tgt[s] = packf2(w0[s], w1[s]);
                #pragma unroll
                for (int u=0;u<2;u++) As2[akl[u]][abl[u]] = packf2(av[u], av[u]);
                __syncthreads();
            }
        }
    }

    const int j = j0 + 2*tx;
    const int b = b0 + ty;
    float ir0,ir1,iz0,iz1,in0,in1, hr0,hr1,hz0,hz1,hn0,hn1;
    unpackf2(i0, ir0,ir1); unpackf2(i1, iz0,iz1); unpackf2(i2, in0,in1);
    unpackf2(h0, hr0,hr1); unpackf2(h1, hz0,hz1); unpackf2(h2, hn0,hn1);
    #pragma unroll
    for (int jj=0;jj<2;jj++){
        float giR = __fadd_rn(jj?ir1:ir0, bi[j+jj]);
        float giZ = __fadd_rn(jj?iz1:iz0, bi[HH+j+jj]);
        float giN = __fadd_rn(jj?in1:in0, bi[2*HH+j+jj]);
        float ghR = __fadd_rn(jj?hr1:hr0, bh[j+jj]);
        float ghZ = __fadd_rn(jj?hz1:hz0, bh[HH+j+jj]);
        float ghN = __fadd_rn(jj?hn1:hn0, bh[2*HH+j+jj]);
        float r = xla_sigmoid(__fadd_rn(giR, ghR));
        float z = xla_sigmoid(__fadd_rn(giZ, ghZ));
        float n = xla_tanh(__fadd_rn(giN, __fmul_rn(r, ghN)));
        float hp = h_in[(size_t)b*HH + j+jj];
        float hn = __fadd_rn(__fmul_rn(__fsub_rn(1.f,z),n), __fmul_rn(z,hp));
        h_out[(size_t)b*HH + j+jj] = hn;
        // emit bf16 planes of h for the tensor-core vocab GEMM
        __nv_bfloat16 p0 = __float2bfloat16_rn(hn);
        float q1 = __fsub_rn(hn, __bfloat162float(p0));
        __nv_bfloat16 p1 = __float2bfloat16_rn(q1);
        float q2 = __fsub_rn(q1, __bfloat162float(p1));
        __nv_bfloat16 p2 = __float2bfloat16_rn(q2);
        int off = b*HH + j+jj;
        g_hb[0*BB*HH + off] = p0;
        g_hb[1*BB*HH + off] = p1;
        g_hb[2*BB*HH + off] = p2;
    }
}

// ---------------- We -> 3 bf16 planes (row-major, zero-padded) -------------
__global__ __launch_bounds__(256) void wsplit_k(const float* __restrict__ We)
{
    const int n = blockIdx.x;          // 0..NPAD-1
    const int tid = threadIdx.x;
    for (int k = tid; k < HH; k += 256){
        float x = (n < VV) ? We[(size_t)n*HH + k] : 0.f;
        __nv_bfloat16 b0 = __float2bfloat16_rn(x);
        float r1 = __fsub_rn(x, __bfloat162float(b0));
        __nv_bfloat16 b1 = __float2bfloat16_rn(r1);
        float r2 = __fsub_rn(r1, __bfloat162float(b1));
        __nv_bfloat16 b2 = __float2bfloat16_rn(r2);
        size_t off = (size_t)n*HH + k;
        g_wb[0*(size_t)NPAD*HH + off] = b0;
        g_wb[1*(size_t)NPAD*HH + off] = b1;
        g_wb[2*(size_t)NPAD*HH + off] = b2;
    }
}

// ---------------- tensor-core (HMMA) vocab GEMM ----------------------------
// logits[128,20000] = h @ We^T + be via 6 bf16 plane-pair GEMMs, one fp32
// accumulator set. Block: 128m x 128n; 8 warps (2m x 4n), warp 64m x 32n.
__global__ __launch_bounds__(256,2) void vgemm_mma_k(const float* __restrict__ bias,
                                                     float* __restrict__ C)
{
    __shared__ __align__(16) __nv_bfloat16 As[2][128][40];
    __shared__ __align__(16) __nv_bfloat16 Bs[2][128][40];
    const int tid  = threadIdx.x;
    const int lane = tid & 31;
    const int w    = tid >> 5;
    const int bn0  = blockIdx.x*128;
    const int m0w  = (w >> 2)*64;
    const int n0w  = (w & 3)*32;
    const unsigned sA = smem_u32(&As[0][0][0]);
    const unsigned sB = smem_u32(&Bs[0][0][0]);

    float d[4][4][4];
    #pragma unroll
    for (int mt=0;mt<4;mt++)
        #pragma unroll
        for (int nt=0;nt<4;nt++)
            #pragma unroll
            for (int e=0;e<4;e++) d[mt][nt][e]=0.f;

    // stage chunk c into buffer buf (A: 512 x16B, B: 512 x16B; 4 cp/thread)
    #define STAGE(c, buf) do { \
        int _pass = (c) >> 4, _k0 = ((c) & 15)*32; \
        const __nv_bfloat16* _Ap = g_hb + c_PI[_pass]*(BB*HH); \
        const __nv_bfloat16* _Bp = g_wb + (size_t)c_PJ[_pass]*((size_t)NPAD*HH); \
        _Pragma("unroll") \
        for (int _s=0;_s<2;_s++){ \
            int _i = tid + _s*256; \
            int _row = _i >> 2, _seg = _i & 3; \
            cpasync16(sA + (buf)*10240u + _row*80u + _seg*16u, \
                      _Ap + (size_t)_row*HH + _k0 + _seg*8); \
            cpasync16(sB + (buf)*10240u + _row*80u + _seg*16u, \
                      _Bp + (size_t)(bn0+_row)*HH + _k0 + _seg*8); \
        } \
        CP_COMMIT(); \
    } while(0)

    STAGE(0, 0);
    for (int c=0; c<96; c++){
        if (c < 95){ STAGE(c+1, (c+1)&1); CP_WAIT1(); }
        else       { CP_WAIT0(); }
        __syncthreads();
        const unsigned bufo = (unsigned)(c&1)*10240u;
        #pragma unroll
        for (int kh=0; kh<2; kh++){
            unsigned a[4][4];
            {
                const int grp = lane >> 3, r = lane & 7;
                const int arow_base = r + (grp & 1)*8;
                const int acol = kh*16 + (grp >> 1)*8;
                #pragma unroll
                for (int mt=0;mt<4;mt++){
                    int row = m0w + mt*16 + arow_base;
                    ldsm_x4(a[mt][0],a[mt][1],a[mt][2],a[mt][3],
                            sA + bufo + row*80u + acol*2u);
                }
            }
            {
                const int l16 = lane & 15;
                const int r = l16 & 7, half = l16 >> 3;
                const int bcol = kh*16 + half*8;
                #pragma unroll
                for (int nt=0;nt<4;nt++){
                    int row = n0w + nt*8 + r;
                    unsigned b0, b1;
                    ldsm_x2(b0, b1, sB + bufo + row*80u + bcol*2u);
                    #pragma unroll
                    for (int mt=0;mt<4;mt++)
                        mma16816(d[mt][nt], a[mt][0],a[mt][1],a[mt][2],a[mt][3], b0, b1);
                }
            }
        }
        __syncthreads();
    }
    #undef STAGE

    // epilogue
    #pragma unroll
    for (int mt=0;mt<4;mt++){
        int m = m0w + mt*16 + (lane >> 2);
        #pragma unroll
        for (int nt=0;nt<4;nt++){
            int n = bn0 + n0w + nt*8 + (lane & 3)*2;
            if (n < VV){
                C[(size_t)m*VV + n  ]       = __fadd_rn(d[mt][nt][0], bias[n  ]);
                C[(size_t)m*VV + n+1]       = __fadd_rn(d[mt][nt][1], bias[n+1]);
                C[(size_t)(m+8)*VV + n  ]   = __fadd_rn(d[mt][nt][2], bias[n  ]);
                C[(size_t)(m+8)*VV + n+1]   = __fadd_rn(d[mt][nt][3], bias[n+1]);
            }
        }
    }
}

// ---------------- fused softmax (logp + argmax) + rate head ---------------
__global__ __launch_bounds__(256) void softrate_k(
    float* __restrict__ out, int step, const float* __restrict__ hcur,
    const float* __restrict__ emb,
    const float* __restrict__ W1, const float* __restrict__ b1,
    const float* __restrict__ W2, const float* __restrict__ b2)
{
    int b = blockIdx.x, tid = threadIdx.x;
    __shared__ float  sv[256];
    __shared__ int    si[256];
    __shared__ double sd[256];
    __shared__ float  xc[EDIM+HH];
    __shared__ double red[256];

    const float* row = g_logits + (size_t)b*VV;
    float m = -3.4e38f;
    for (int k=tid;k<VV;k+=256) m = fmaxf(m, row[k]);
    sv[tid]=m; __syncthreads();
    for (int s=128;s>0;s>>=1){ if (tid<s) sv[tid]=fmaxf(sv[tid],sv[tid+s]); __syncthreads(); }
    float mx = sv[0];
    __syncthreads();
    float ps=0.f; double pd=0.0; int cnt=0;
    for (int k=tid;k<VV;k+=256){
        ps += expf(__fsub_rn(row[k], mx));
        if (++cnt==16){ pd += (double)ps; ps=0.f; cnt=0; }
    }
    pd += (double)ps;
    sd[tid]=pd; __syncthreads();
    for (int st=128;st>0;st>>=1){ if (tid<st) sd[tid]+=sd[tid+st]; __syncthreads(); }
    float lsh = logf((float)sd[0]);
    float* o = out + ((size_t)step*BB + b)*VV;
    float bm = -3.4e38f; int bi_ = VV;
    for (int k=tid;k<VV;k+=256){
        float v = __fsub_rn(__fsub_rn(row[k], mx), lsh);
        o[k] = v;
        if (v>bm || (v==bm && k<bi_)){ bm=v; bi_=k; }
    }
    sv[tid]=bm; si[tid]=bi_; __syncthreads();
    for (int s=128;s>0;s>>=1){
        if (tid<s){
            float v2=sv[tid+s]; int i2=si[tid+s];
            if (v2>sv[tid] || (v2==sv[tid] && i2<si[tid])){ sv[tid]=v2; si[tid]=i2; }
        }
        __syncthreads();
    }
    int e = si[0];
    if (tid==0) g_eid[b] = e;
    __syncthreads();

    if (tid < EDIM) xc[tid] = emb[(size_t)e*EDIM + tid];
    for (int k=tid;k<HH;k+=256) xc[EDIM+k] = hcur[(size_t)b*HH + k];
    __syncthreads();
    double partial = 0.0;
    for (int j=tid;j<HH;j+=256){
        const float* w = W1 + (size_t)j*(EDIM+HH);
        float acc = 0.f;
        #pragma unroll 8
        for (int k=0;k<EDIM+HH;k+=4){
            float4 wv = *(const float4*)(w+k);
            acc = fmaf(wv.x, xc[k],   acc);
            acc = fmaf(wv.y, xc[k+1], acc);
            acc = fmaf(wv.z, xc[k+2], acc);
            acc = fmaf(wv.w, xc[k+3], acc);
        }
        float pre = __fadd_rn(acc, b1[j]);
        partial += (double)__fmul_rn(fmaxf(pre, 0.f), W2[j]);
    }
    red[tid]=partial; __syncthreads();
    for (int s=128;s>0;s>>=1){ if (tid<s) red[tid]+=red[tid+s]; __syncthreads(); }
    if (tid==0){
        float y = __fadd_rn((float)red[0], b2[0]);
        float pr = xla_sigmoid(y);
        out[(size_t)TTRG*BB*VV + step*BB + b] = pr;
        g_rate[b] = pr;
    }
}

// ---------------- init ----------------------------------------------------
__global__ void init_k(float* __restrict__ out, const int* __restrict__ trg_eid,
                       const float* __restrict__ trg_rate)
{
    long long i = (long long)blockIdx.x*blockDim.x + threadIdx.x;
    const long long RATE_OFF = (long long)TTRG*BB*VV;
    if (i < (long long)BB*VV) out[i] = 0.f;
    if (i < BB)               out[RATE_OFF + i] = 0.f;
    if (i < BB*HH)            g_h[i] = 0.f;
    if (i < BB){ g_eid[i] = trg_eid[i]; g_rate[i] = trg_rate[i]; }
}

// ---------------- launch ---------------------------------------------------
extern "C" void kernel_launch(void* const* d_in, const int* in_sizes, int n_in,
                              void* d_out, int out_size)
{
    const float* src      = (const float*)d_in[0];
    const int*   src_len  = (const int*)  d_in[1];
    const int*   trg_eid  = (const int*)  d_in[2];
    const float* trg_rate = (const float*)d_in[3];
    const float* emb      = (const float*)d_in[4];
    const float* enc_Wi   = (const float*)d_in[5];
    const float* enc_Wh   = (const float*)d_in[6];
    const float* enc_bi   = (const float*)d_in[7];
    const float* enc_bh   = (const float*)d_in[8];
    const float* dec_Wi   = (const float*)d_in[9];
    const float* dec_Wh   = (const float*)d_in[10];
    const float* dec_bi   = (const float*)d_in[11];
    const float* dec_bh   = (const float*)d_in[12];
    const float* We       = (const float*)d_in[13];
    const float* be       = (const float*)d_in[14];
    const float* W1       = (const float*)d_in[15];
    const float* b1       = (const float*)d_in[16];
    const float* W2       = (const float*)d_in[17];
    const float* b2       = (const float*)d_in[18];
    float* out = (float*)d_out;

    float *p_h, *p_h2, *p_gi_enc, *p_logits;
    cudaGetSymbolAddress((void**)&p_h,      g_h);
    cudaGetSymbolAddress((void**)&p_h2,     g_h2);
    cudaGetSymbolAddress((void**)&p_gi_enc, g_gi_enc);
    cudaGetSymbolAddress((void**)&p_logits, g_logits);

    float* hb[2] = {p_h, p_h2};
    int par = 0;

    init_k<<<10000,256>>>(out, trg_eid, trg_rate);

    sgemm_k<64,64,32,4,4><<<dim3(G3H/64, (TSRC*BB)/64), dim3(16,16)>>>(
        src, INDIM, enc_Wi, enc_bi, p_gi_enc, TSRC*BB, G3H, INDIM);

    // one-time (per replay) We bf16-plane precompute
    wsplit_k<<<NPAD, 256>>>(We);

    for (int t=0;t<TSRC;t++){
        gru_enc_f<<<dim3(HH/32, BB/16), 256>>>(
            hb[par], hb[par^1], enc_Wh, enc_bh,
            p_gi_enc + (size_t)t*BB*G3H, src_len, t);
        par ^= 1;
    }

    for (int step=1; step<TTRG; step++){
        gru_dec_f<<<dim3(HH/32, BB/16), 256>>>(
            hb[par], hb[par^1], dec_Wi, dec_bi, dec_Wh, dec_bh, emb);
        par ^= 1;
        vgemm_mma_k<<<NT2, 256>>>(be, p_logits);
        softrate_k<<<BB,256>>>(out, step, hb[par], emb, W1, b1, W2, b2);
    }
}

// round 17
// speedup vs baseline: 2.4896x; 1.1798x over previous
#include <cuda_runtime.h>
#include <cuda_bf16.h>
#include <math.h>

#define BB   128
#define HH   512
#define INDIM 256
#define EDIM 256
#define VV   20000
#define TSRC 64
#define TTRG 50
#define G3H  1536
#define KX   257
#define NT2  157            // ceil(VV/128)
#define NPAD (NT2*128)      // 20096

// ---------------- scratch (device globals; no allocation) ----------------
__device__ float g_h [BB*HH];
__device__ float g_h2[BB*HH];
__device__ float g_gi_enc[(size_t)TSRC*BB*G3H];
__device__ float g_logits[(size_t)BB*VV];
__device__ int   g_eid[BB];
__device__ float g_rate[BB];
__device__ __align__(16) __nv_bfloat16 g_hb[2*BB*HH];              // h planes
__device__ __align__(16) __nv_bfloat16 g_wb[(size_t)2*NPAD*HH];    // We planes

__constant__ int c_PI[3] = {0,0,1};
__constant__ int c_PJ[3] = {0,1,0};

// ---- XLA f32 tanh (rational approx) + logistic expansion, no FMA fusion --
__device__ __forceinline__ float xla_tanh(float x){
    float ax = fabsf(x);
    float xc = fmaxf(-7.90531110763549805f, fminf(7.90531110763549805f, x));
    float x2 = __fmul_rn(xc, xc);
    float np = -2.76076847742355e-16f;
    np = __fadd_rn(__fmul_rn(np, x2),  2.00018790482477e-13f);
    np = __fadd_rn(__fmul_rn(np, x2), -8.60467152213735e-11f);
    np = __fadd_rn(__fmul_rn(np, x2),  5.12229709037114e-08f);
    np = __fadd_rn(__fmul_rn(np, x2),  1.48572235717979e-05f);
    np = __fadd_rn(__fmul_rn(np, x2),  6.37261928875436e-04f);
    np = __fadd_rn(__fmul_rn(np, x2),  4.89352455891786e-03f);
    np = __fmul_rn(np, xc);
    float dp = 1.19825839466702e-06f;
    dp = __fadd_rn(__fmul_rn(dp, x2), 1.18534705686654e-04f);
    dp = __fadd_rn(__fmul_rn(dp, x2), 2.26843463243900e-03f);
    dp = __fadd_rn(__fmul_rn(dp, x2), 4.89352518554385e-03f);
    float r = __fdiv_rn(np, dp);
    return (ax < 0.0004f) ? x : r;
}
__device__ __forceinline__ float xla_sigmoid(float x){
    return __fadd_rn(0.5f, __fmul_rn(0.5f, xla_tanh(__fmul_rn(0.5f, x))));
}

// ---- packed f32x2 helpers --------------------------------------------------
__device__ __forceinline__ unsigned long long packf2(float lo, float hi){
    unsigned long long r;
    asm("mov.b64 %0, {%1, %2};" : "=l"(r)
        : "r"(__float_as_uint(lo)), "r"(__float_as_uint(hi)));
    return r;
}
__device__ __forceinline__ void unpackf2(unsigned long long v, float& lo, float& hi){
    unsigned int a, b;
    asm("mov.b64 {%0, %1}, %2;" : "=r"(a), "=r"(b) : "l"(v));
    lo = __uint_as_float(a); hi = __uint_as_float(b);
}
__device__ __forceinline__ unsigned long long ffma2(
    unsigned long long a, unsigned long long b, unsigned long long c){
    unsigned long long d;
    asm("fma.rn.f32x2 %0, %1, %2, %3;" : "=l"(d) : "l"(a), "l"(b), "l"(c));
    return d;
}

// ---- mma / ldmatrix / cp.async helpers (base-target features) -------------
__device__ __forceinline__ unsigned smem_u32(const void* p){
    unsigned a;
    asm("{ .reg .u64 t; cvta.to.shared.u64 t, %1; cvt.u32.u64 %0, t; }"
        : "=r"(a) : "l"(p));
    return a;
}
__device__ __forceinline__ void ldsm_x4(unsigned&r0,unsigned&r1,unsigned&r2,unsigned&r3,
                                        unsigned addr){
    asm volatile("ldmatrix.sync.aligned.m8n8.x4.shared.b16 {%0,%1,%2,%3}, [%4];"
        : "=r"(r0),"=r"(r1),"=r"(r2),"=r"(r3) : "r"(addr));
}
__device__ __forceinline__ void ldsm_x2(unsigned&r0,unsigned&r1, unsigned addr){
    asm volatile("ldmatrix.sync.aligned.m8n8.x2.shared.b16 {%0,%1}, [%2];"
        : "=r"(r0),"=r"(r1) : "r"(addr));
}
__device__ __forceinline__ void mma16816(float* d, unsigned a0,unsigned a1,
                                         unsigned a2,unsigned a3,
                                         unsigned b0,unsigned b1){
    asm volatile("mma.sync.aligned.m16n8k16.row.col.f32.bf16.bf16.f32 "
        "{%0,%1,%2,%3}, {%4,%5,%6,%7}, {%8,%9}, {%0,%1,%2,%3};"
        : "+f"(d[0]),"+f"(d[1]),"+f"(d[2]),"+f"(d[3])
        : "r"(a0),"r"(a1),"r"(a2),"r"(a3),"r"(b0),"r"(b1));
}
__device__ __forceinline__ void cpasync16(unsigned saddr, const void* g){
    asm volatile("cp.async.cg.shared.global [%0], [%1], 16;" :: "r"(saddr), "l"(g));
}
#define CP_COMMIT() asm volatile("cp.async.commit_group;")
#define CP_WAIT1()  asm volatile("cp.async.wait_group 1;")
#define CP_WAIT0()  asm volatile("cp.async.wait_group 0;")

// ---------------- plain SGEMM (encoder-Wi precompute only) ----------------
template<int BM,int BN,int BK,int TM,int TN>
__global__ void sgemm_k(const float* __restrict__ A, int lda,
                        const float* __restrict__ W,
                        const float* __restrict__ bias,
                        float* __restrict__ C,
                        int M, int N, int K)
{
    __shared__ float As[BK][BM+4];
    __shared__ float Ws[BK][BN+4];
    constexpr int NT = (BM/TM)*(BN/TN);
    const int tx = threadIdx.x;
    const int ty = threadIdx.y;
    const int tid = ty*(BN/TN)+tx;
    const int bm0 = blockIdx.y*BM;
    const int bn0 = blockIdx.x*BN;

    float acc[TM][TN];
    #pragma unroll
    for (int i=0;i<TM;i++)
        #pragma unroll
        for (int j=0;j<TN;j++) acc[i][j]=0.f;

    for (int k0=0;k0<K;k0+=BK){
        for (int i=tid;i<BM*BK;i+=NT){
            int kl=i%BK, ml=i/BK;
            int m=bm0+ml, kg=k0+kl;
            As[kl][ml] = (m<M && kg<K) ? A[(size_t)m*lda + kg] : 0.f;
        }
        for (int i=tid;i<BN*BK;i+=NT){
            int kl=i%BK, nl=i/BK;
            int n=bn0+nl, kg=k0+kl;
            Ws[kl][nl] = (n<N && kg<K) ? W[(size_t)n*K + kg] : 0.f;
        }
        __syncthreads();
        #pragma unroll
        for (int kk=0;kk<BK;kk++){
            float a[TM], b[TN];
            #pragma unroll
            for (int i=0;i<TM;i+=4){
                float4 v = *(const float4*)&As[kk][ty*TM+i];
                a[i]=v.x; a[i+1]=v.y; a[i+2]=v.z; a[i+3]=v.w;
            }
            #pragma unroll
            for (int j=0;j<TN;j+=4){
                float4 v = *(const float4*)&Ws[kk][tx*TN+j];
                b[j]=v.x; b[j+1]=v.y; b[j+2]=v.z; b[j+3]=v.w;
            }
            #pragma unroll
            for (int i=0;i<TM;i++)
                #pragma unroll
                for (int j=0;j<TN;j++)
                    acc[i][j] = fmaf(a[i], b[j], acc[i][j]);
        }
        __syncthreads();
    }
    #pragma unroll
    for (int i=0;i<TM;i++){
        int m=bm0+ty*TM+i;
        if (m>=M) continue;
        #pragma unroll
        for (int j=0;j<TN;j++){
            int n=bn0+tx*TN+j;
            if (n<N) C[(size_t)m*N+n] = __fadd_rn(acc[i][j], bias[n]);
        }
    }
}

// ============ fused GRU step kernels (R12, bit-identical h math) ===========
__global__ __launch_bounds__(256) void gru_enc_f(
    const float* __restrict__ h_in, float* __restrict__ h_out,
    const float* __restrict__ Wh, const float* __restrict__ bh,
    const float* __restrict__ gi_t,
    const int* __restrict__ src_len, int t)
{
    __shared__ unsigned long long As2[32][17];
    __shared__ unsigned long long Wv[3][16][34];
    const int tid = threadIdx.x;
    const int tx = tid & 15;
    const int ty = tid >> 4;
    const int j0 = blockIdx.x*32;
    const int b0 = blockIdx.y*16;

    int w_off[6]; unsigned long long* w_tgt[6];
    #pragma unroll
    for (int s=0;s<6;s++){
        int i = tid + s*256;
        int kl = i & 31, r = i >> 5, jp = r & 15, g = r >> 4;
        w_off[s] = (g*HH + j0 + 2*jp)*HH + kl;
        w_tgt[s] = &Wv[g][jp][kl];
    }
    int a_off[2]; unsigned long long* a_tgt[2];
    #pragma unroll
    for (int u=0;u<2;u++){
        int i = tid + u*256;
        a_off[u] = (b0 + (i>>5))*HH + (i&31);
        a_tgt[u] = &As2[i&31][i>>5];
    }

    unsigned long long ac0=0ull, ac1=0ull, ac2=0ull;
    float w0[6], w1[6], av[2];

    #pragma unroll
    for (int s=0;s<6;s++){ w0[s]=Wh[w_off[s]]; w1[s]=Wh[w_off[s]+HH]; }
    #pragma unroll
    for (int u=0;u<2;u++) av[u]=h_in[a_off[u]];
    #pragma unroll
    for (int s=0;s<6;s++) *w_tgt[s] = packf2(w0[s], w1[s]);
    #pragma unroll
    for (int u=0;u<2;u++) *a_tgt[u] = packf2(av[u], av[u]);
    __syncthreads();

    for (int kt=0; kt<16; kt++){
        const int k1 = (kt+1)*32;
        if (kt<15){
            #pragma unroll
            for (int s=0;s<6;s++){ w0[s]=Wh[w_off[s]+k1]; w1[s]=Wh[w_off[s]+HH+k1]; }
            #pragma unroll
            for (int u=0;u<2;u++) av[u]=h_in[a_off[u]+k1];
        }
        #pragma unroll
        for (int kk=0;kk<32;kk+=2){
            ulonglong2 wr = *(const ulonglong2*)&Wv[0][tx][kk];
            ulonglong2 wz = *(const ulonglong2*)&Wv[1][tx][kk];
            ulonglong2 wn = *(const ulonglong2*)&Wv[2][tx][kk];
            unsigned long long a0 = As2[kk][ty];
            unsigned long long a1 = As2[kk+1][ty];
            ac0 = ffma2(a0, wr.x, ac0);
            ac1 = ffma2(a0, wz.x, ac1);
            ac2 = ffma2(a0, wn.x, ac2);
            ac0 = ffma2(a1, wr.y, ac0);
            ac1 = ffma2(a1, wz.y, ac1);
            ac2 = ffma2(a1, wn.y, ac2);
        }
        __syncthreads();
        if (kt<15){
            #pragma unroll
            for (int s=0;s<6;s++) *w_tgt[s] = packf2(w0[s], w1[s]);
            #pragma unroll
            for (int u=0;u<2;u++) *a_tgt[u] = packf2(av[u], av[u]);
            __syncthreads();
        }
    }

    const int j = j0 + 2*tx;
    const int b = b0 + ty;
    const float* gi = gi_t + (size_t)b*G3H;
    float dr0,dr1,dz0,dz1,dn0,dn1;
    unpackf2(ac0, dr0,dr1);
    unpackf2(ac1, dz0,dz1);
    unpackf2(ac2, dn0,dn1);
    int frozen = (t >= src_len[b]);
    #pragma unroll
    for (int jj=0;jj<2;jj++){
        float gr = __fadd_rn(jj?dr1:dr0, bh[j+jj]);
        float gz = __fadd_rn(jj?dz1:dz0, bh[HH+j+jj]);
        float gn = __fadd_rn(jj?dn1:dn0, bh[2*HH+j+jj]);
        float r = xla_sigmoid(__fadd_rn(gi[j+jj],      gr));
        float z = xla_sigmoid(__fadd_rn(gi[HH+j+jj],   gz));
        float n = xla_tanh(__fadd_rn(gi[2*HH+j+jj], __fmul_rn(r, gn)));
        float hp = h_in[(size_t)b*HH + j+jj];
        float hn = __fadd_rn(__fmul_rn(__fsub_rn(1.f,z),n), __fmul_rn(z,hp));
        h_out[(size_t)b*HH + j+jj] = frozen ? hp : hn;
    }
}

__global__ __launch_bounds__(256) void gru_dec_f(
    const float* __restrict__ h_in, float* __restrict__ h_out,
    const float* __restrict__ Wi, const float* __restrict__ bi,
    const float* __restrict__ Wh, const float* __restrict__ bh,
    const float* __restrict__ emb)
{
    __shared__ unsigned long long As2[32][17];
    __shared__ unsigned long long Wv[3][16][34];
    __shared__ int   seid[16];
    __shared__ float srate[16];
    const int tid = threadIdx.x;
    const int tx = tid & 15;
    const int ty = tid >> 4;
    const int j0 = blockIdx.x*32;
    const int b0 = blockIdx.y*16;

    if (tid < 16){ seid[tid] = g_eid[b0+tid]; srate[tid] = g_rate[b0+tid]; }
    __syncthreads();

    int klv[6], jpv[6], gv[6];
    unsigned long long* w_tgt[6];
    #pragma unroll
    for (int s=0;s<6;s++){
        int i = tid + s*256;
        klv[s] = i & 31; int r = i >> 5; jpv[s] = r & 15; gv[s] = r >> 4;
        w_tgt[s] = &Wv[gv[s]][jpv[s]][klv[s]];
    }
    int akl[2], abl[2];
    #pragma unroll
    for (int u=0;u<2;u++){
        int i = tid + u*256;
        akl[u] = i & 31; abl[u] = i >> 5;
    }

    unsigned long long i0=0ull, i1=0ull, i2=0ull;
    unsigned long long h0=0ull, h1=0ull, h2=0ull;
    float w0[6], w1[6], av[2];

    {
        int wI_off[6], aI_off[2];
        #pragma unroll
        for (int s=0;s<6;s++)
            wI_off[s] = (gv[s]*HH + j0 + 2*jpv[s])*KX + klv[s];
        #pragma unroll
        for (int u=0;u<2;u++)
            aI_off[u] = seid[abl[u]]*EDIM + akl[u];

        #pragma unroll
        for (int s=0;s<6;s++){ w0[s]=Wi[wI_off[s]]; w1[s]=Wi[wI_off[s]+KX]; }
        #pragma unroll
        for (int u=0;u<2;u++) av[u]=emb[aI_off[u]];
        #pragma unroll
        for (int s=0;s<6;s++) *w_tgt[s] = packf2(w0[s], w1[s]);
        #pragma unroll
        for (int u=0;u<2;u++) As2[akl[u]][abl[u]] = packf2(av[u], av[u]);
        __syncthreads();

        for (int kt=0; kt<8; kt++){
            const int k1 = (kt+1)*32;
            if (kt<7){
                #pragma unroll
                for (int s=0;s<6;s++){ w0[s]=Wi[wI_off[s]+k1]; w1[s]=Wi[wI_off[s]+KX+k1]; }
                #pragma unroll
                for (int u=0;u<2;u++) av[u]=emb[aI_off[u]+k1];
            }
            #pragma unroll
            for (int kk=0;kk<32;kk+=2){
                ulonglong2 wr = *(const ulonglong2*)&Wv[0][tx][kk];
                ulonglong2 wz = *(const ulonglong2*)&Wv[1][tx][kk];
                ulonglong2 wn = *(const ulonglong2*)&Wv[2][tx][kk];
                unsigned long long a0 = As2[kk][ty];
                unsigned long long a1 = As2[kk+1][ty];
                i0 = ffma2(a0, wr.x, i0);
                i1 = ffma2(a0, wz.x, i1);
                i2 = ffma2(a0, wn.x, i2);
                i0 = ffma2(a1, wr.y, i0);
                i1 = ffma2(a1, wz.y, i1);
                i2 = ffma2(a1, wn.y, i2);
            }
            __syncthreads();
            if (kt<7){
                #pragma unroll
                for (int s=0;s<6;s++) *w_tgt[s] = packf2(w0[s], w1[s]);
                #pragma unroll
                for (int u=0;u<2;u++) As2[akl[u]][abl[u]] = packf2(av[u], av[u]);
                __syncthreads();
            }
        }
    }
    {
        const int j = j0 + 2*tx;
        float rv = srate[ty];
        unsigned long long rp = packf2(rv, rv);
        unsigned long long wt;
        wt = packf2(Wi[(0*HH + j)*KX + 256], Wi[(0*HH + j+1)*KX + 256]);
        i0 = ffma2(rp, wt, i0);
        wt = packf2(Wi[(1*HH + j)*KX + 256], Wi[(1*HH + j+1)*KX + 256]);
        i1 = ffma2(rp, wt, i1);
        wt = packf2(Wi[(2*HH + j)*KX + 256], Wi[(2*HH + j+1)*KX + 256]);
        i2 = ffma2(rp, wt, i2);
    }
    {
        int wH_off[6], aH_off[2];
        #pragma unroll
        for (int s=0;s<6;s++)
            wH_off[s] = (gv[s]*HH + j0 + 2*jpv[s])*HH + klv[s];
        #pragma unroll
        for (int u=0;u<2;u++)
            aH_off[u] = (b0 + abl[u])*HH + akl[u];

        #pragma unroll
        for (int s=0;s<6;s++){ w0[s]=Wh[wH_off[s]]; w1[s]=Wh[wH_off[s]+HH]; }
        #pragma unroll
        for (int u=0;u<2;u++) av[u]=h_in[aH_off[u]];
        #pragma unroll
        for (int s=0;s<6;s++) *w_tgt[s] = packf2(w0[s], w1[s]);
        #pragma unroll
        for (int u=0;u<2;u++) As2[akl[u]][abl[u]] = packf2(av[u], av[u]);
        __syncthreads();

        for (int kt=0; kt<16; kt++){
            const int k1 = (kt+1)*32;
            if (kt<15){
                #pragma unroll
                for (int s=0;s<6;s++){ w0[s]=Wh[wH_off[s]+k1]; w1[s]=Wh[wH_off[s]+HH+k1]; }
                #pragma unroll
                for (int u=0;u<2;u++) av[u]=h_in[aH_off[u]+k1];
            }
            #pragma unroll
            for (int kk=0;kk<32;kk+=2){
                ulonglong2 wr = *(const ulonglong2*)&Wv[0][tx][kk];
                ulonglong2 wz = *(const ulonglong2*)&Wv[1][tx][kk];
                ulonglong2 wn = *(const ulonglong2*)&Wv[2][tx][kk];
                unsigned long long a0 = As2[kk][ty];
                unsigned long long a1 = As2[kk+1][ty];
                h0 = ffma2(a0, wr.x, h0);
                h1 = ffma2(a0, wz.x, h1);
                h2 = ffma2(a0, wn.x, h2);
                h0 = ffma2(a1, wr.y, h0);
                h1 = ffma2(a1, wz.y, h1);
                h2 = ffma2(a1, wn.y, h2);
            }
            __syncthreads();
            if (kt<15){
                #pragma unroll
                for (int s=0;s<6;s++) *w_tgt[s] = packf2(w0[s], w1[s]);
                #pragma unroll
                for (int u=0;u<2;u++) As2[akl[u]][abl[u]] = packf2(av[u], av[u]);
                __syncthreads();
            }
        }
    }

    const int j = j0 + 2*tx;
    const int b = b0 + ty;
    float ir0,ir1,iz0,iz1,in0,in1, hr0,hr1,hz0,hz1,hn0,hn1;
    unpackf2(i0, ir0,ir1); unpackf2(i1, iz0,iz1); unpackf2(i2, in0,in1);
    unpackf2(h0, hr0,hr1); unpackf2(h1, hz0,hz1); unpackf2(h2, hn0,hn1);
    #pragma unroll
    for (int jj=0;jj<2;jj++){
        float giR = __fadd_rn(jj?ir1:ir0, bi[j+jj]);
        float giZ = __fadd_rn(jj?iz1:iz0, bi[HH+j+jj]);
        float giN = __fadd_rn(jj?in1:in0, bi[2*HH+j+jj]);
        float ghR = __fadd_rn(jj?hr1:hr0, bh[j+jj]);
        float ghZ = __fadd_rn(jj?hz1:hz0, bh[HH+j+jj]);
        float ghN = __fadd_rn(jj?hn1:hn0, bh[2*HH+j+jj]);
        float r = xla_sigmoid(__fadd_rn(giR, ghR));
        float z = xla_sigmoid(__fadd_rn(giZ, ghZ));
        float n = xla_tanh(__fadd_rn(giN, __fmul_rn(r, ghN)));
        float hp = h_in[(size_t)b*HH + j+jj];
        float hn = __fadd_rn(__fmul_rn(__fsub_rn(1.f,z),n), __fmul_rn(z,hp));
        h_out[(size_t)b*HH + j+jj] = hn;
        // emit bf16 planes of h for the tensor-core vocab GEMM (2 planes)
        __nv_bfloat16 p0 = __float2bfloat16_rn(hn);
        float q1 = __fsub_rn(hn, __bfloat162float(p0));
        __nv_bfloat16 p1 = __float2bfloat16_rn(q1);
        int off = b*HH + j+jj;
        g_hb[0*BB*HH + off] = p0;
        g_hb[1*BB*HH + off] = p1;
    }
}

// ---------------- We -> 2 bf16 planes (row-major, zero-padded) -------------
__global__ __launch_bounds__(256) void wsplit_k(const float* __restrict__ We)
{
    const int n = blockIdx.x;          // 0..NPAD-1
    const int tid = threadIdx.x;
    for (int k = tid; k < HH; k += 256){
        float x = (n < VV) ? We[(size_t)n*HH + k] : 0.f;
        __nv_bfloat16 b0 = __float2bfloat16_rn(x);
        float r1 = __fsub_rn(x, __bfloat162float(b0));
        __nv_bfloat16 b1 = __float2bfloat16_rn(r1);
        size_t off = (size_t)n*HH + k;
        g_wb[0*(size_t)NPAD*HH + off] = b0;
        g_wb[1*(size_t)NPAD*HH + off] = b1;
    }
}

// ---------------- tensor-core (HMMA) vocab GEMM: 3 plane-pair passes -------
__global__ __launch_bounds__(256,2) void vgemm_mma_k(const float* __restrict__ bias,
                                                     float* __restrict__ C)
{
    __shared__ __align__(16) __nv_bfloat16 As[2][128][40];
    __shared__ __align__(16) __nv_bfloat16 Bs[2][128][40];
    const int tid  = threadIdx.x;
    const int lane = tid & 31;
    const int w    = tid >> 5;
    const int bn0  = blockIdx.x*128;
    const int m0w  = (w >> 2)*64;
    const int n0w  = (w & 3)*32;
    const unsigned sA = smem_u32(&As[0][0][0]);
    const unsigned sB = smem_u32(&Bs[0][0][0]);

    float d[4][4][4];
    #pragma unroll
    for (int mt=0;mt<4;mt++)
        #pragma unroll
        for (int nt=0;nt<4;nt++)
            #pragma unroll
            for (int e=0;e<4;e++) d[mt][nt][e]=0.f;

    #define STAGE(c, buf) do { \
        int _pass = (c) >> 4, _k0 = ((c) & 15)*32; \
        const __nv_bfloat16* _Ap = g_hb + c_PI[_pass]*(BB*HH); \
        const __nv_bfloat16* _Bp = g_wb + (size_t)c_PJ[_pass]*((size_t)NPAD*HH); \
        _Pragma("unroll") \
        for (int _s=0;_s<2;_s++){ \
            int _i = tid + _s*256; \
            int _row = _i >> 2, _seg = _i & 3; \
            cpasync16(sA + (buf)*10240u + _row*80u + _seg*16u, \
                      _Ap + (size_t)_row*HH + _k0 + _seg*8); \
            cpasync16(sB + (buf)*10240u + _row*80u + _seg*16u, \
                      _Bp + (size_t)(bn0+_row)*HH + _k0 + _seg*8); \
        } \
        CP_COMMIT(); \
    } while(0)

    STAGE(0, 0);
    for (int c=0; c<48; c++){
        if (c < 47){ STAGE(c+1, (c+1)&1); CP_WAIT1(); }
        else       { CP_WAIT0(); }
        __syncthreads();
        const unsigned bufo = (unsigned)(c&1)*10240u;
        #pragma unroll
        for (int kh=0; kh<2; kh++){
            unsigned a[4][4];
            {
                const int grp = lane >> 3, r = lane & 7;
                const int arow_base = r + (grp & 1)*8;
                const int acol = kh*16 + (grp >> 1)*8;
                #pragma unroll
                for (int mt=0;mt<4;mt++){
                    int row = m0w + mt*16 + arow_base;
                    ldsm_x4(a[mt][0],a[mt][1],a[mt][2],a[mt][3],
                            sA + bufo + row*80u + acol*2u);
                }
            }
            {
                const int l16 = lane & 15;
                const int r = l16 & 7, half = l16 >> 3;
                const int bcol = kh*16 + half*8;
                #pragma unroll
                for (int nt=0;nt<4;nt++){
                    int row = n0w + nt*8 + r;
                    unsigned b0, b1;
                    ldsm_x2(b0, b1, sB + bufo + row*80u + bcol*2u);
                    #pragma unroll
                    for (int mt=0;mt<4;mt++)
                        mma16816(d[mt][nt], a[mt][0],a[mt][1],a[mt][2],a[mt][3], b0, b1);
                }
            }
        }
        __syncthreads();
    }
    #undef STAGE

    #pragma unroll
    for (int mt=0;mt<4;mt++){
        int m = m0w + mt*16 + (lane >> 2);
        #pragma unroll
        for (int nt=0;nt<4;nt++){
            int n = bn0 + n0w + nt*8 + (lane & 3)*2;
            if (n < VV){
                C[(size_t)m*VV + n  ]       = __fadd_rn(d[mt][nt][0], bias[n  ]);
                C[(size_t)m*VV + n+1]       = __fadd_rn(d[mt][nt][1], bias[n+1]);
                C[(size_t)(m+8)*VV + n  ]   = __fadd_rn(d[mt][nt][2], bias[n  ]);
                C[(size_t)(m+8)*VV + n+1]   = __fadd_rn(d[mt][nt][3], bias[n+1]);
            }
        }
    }
}

// -- fused softmax (3-pass logp) + R12-chain-bitwise argmax rescue + rate ---
__global__ __launch_bounds__(256) void softrate_k(
    float* __restrict__ out, int step, const float* __restrict__ hcur,
    const float* __restrict__ emb,
    const float* __restrict__ We, const float* __restrict__ be,
    const float* __restrict__ W1, const float* __restrict__ b1,
    const float* __restrict__ W2, const float* __restrict__ b2)
{
    int b = blockIdx.x, tid = threadIdx.x;
    __shared__ float  sv[256];
    __shared__ double sd[256];
    __shared__ float  xc[EDIM+HH];
    __shared__ double red[256];
    __shared__ int    cand[32];
    __shared__ int    ncand;
    __shared__ int    besti;

    const float* row = g_logits + (size_t)b*VV;
    float m = -3.4e38f;
    for (int k=tid;k<VV;k+=256) m = fmaxf(m, row[k]);
    sv[tid]=m; __syncthreads();
    for (int s=128;s>0;s>>=1){ if (tid<s) sv[tid]=fmaxf(sv[tid],sv[tid+s]); __syncthreads(); }
    float mx = sv[0];
    if (tid==0) ncand = 0;
    __syncthreads();
    // candidates within margin (3-pass logit error bound ~8e-5 << 2e-4)
    for (int k=tid;k<VV;k+=256){
        if (row[k] >= mx - 2e-4f){
            int p = atomicAdd(&ncand, 1);
            if (p < 32) cand[p] = k;
        }
    }
    // sum of exp over approx logits (logp output error ~1e-6 rel; fine)
    float ps=0.f; double pd=0.0; int cnt=0;
    for (int k=tid;k<VV;k+=256){
        ps += expf(__fsub_rn(row[k], mx));
        if (++cnt==16){ pd += (double)ps; ps=0.f; cnt=0; }
    }
    pd += (double)ps;
    sd[tid]=pd; __syncthreads();
    for (int st=128;st>0;st>>=1){ if (tid<st) sd[tid]+=sd[tid+st]; __syncthreads(); }
    float lsh = logf((float)sd[0]);
    float* o = out + ((size_t)step*BB + b)*VV;
    for (int k=tid;k<VV;k+=256)
        o[k] = __fsub_rn(__fsub_rn(row[k], mx), lsh);
    __syncthreads();

    // Rescue: recompute candidate logits with the EXACT R12 per-output chain
    // (acc=0; ascending-k fmaf; + bias via __fadd_rn), then logp transform and
    // R12's (value, lower-index) selection. One candidate per lane of warp 0.
    int nc = min(ncand, 32);
    if (tid < 32){
        float lp = -3.4e38f; int idx = VV;
        if (tid < nc){
            int kidx = cand[tid];
            const float* wr = We + (size_t)kidx*HH;
            const float* hr = hcur + (size_t)b*HH;
            float acc = 0.f;
            for (int k=0;k<HH;k++)
                acc = fmaf(hr[k], wr[k], acc);
            float v = __fadd_rn(acc, be[kidx]);
            lp = __fsub_rn(__fsub_rn(v, mx), lsh);
            idx = kidx;
        }
        #pragma unroll
        for (int off=16; off>0; off>>=1){
            float lp2 = __shfl_down_sync(0xffffffffu, lp, off);
            int   i2  = __shfl_down_sync(0xffffffffu, idx, off);
            if (lp2 > lp || (lp2 == lp && i2 < idx)){ lp = lp2; idx = i2; }
        }
        if (tid==0) besti = idx;
    }
    __syncthreads();
    int e = besti;
    if (tid==0) g_eid[b] = e;
    __syncthreads();

    // rate head (unchanged from R12)
    if (tid < EDIM) xc[tid] = emb[(size_t)e*EDIM + tid];
    for (int k=tid;k<HH;k+=256) xc[EDIM+k] = hcur[(size_t)b*HH + k];
    __syncthreads();
    double partial = 0.0;
    for (int j=tid;j<HH;j+=256){
        const float* w = W1 + (size_t)j*(EDIM+HH);
        float acc = 0.f;
        #pragma unroll 8
        for (int k=0;k<EDIM+HH;k+=4){
            float4 wv = *(const float4*)(w+k);
            acc = fmaf(wv.x, xc[k],   acc);
            acc = fmaf(wv.y, xc[k+1], acc);
            acc = fmaf(wv.z, xc[k+2], acc);
            acc = fmaf(wv.w, xc[k+3], acc);
        }
        float pre = __fadd_rn(acc, b1[j]);
        partial += (double)__fmul_rn(fmaxf(pre, 0.f), W2[j]);
    }
    red[tid]=partial; __syncthreads();
    for (int s=128;s>0;s>>=1){ if (tid<s) red[tid]+=red[tid+s]; __syncthreads(); }
    if (tid==0){
        float y = __fadd_rn((float)red[0], b2[0]);
        float pr = xla_sigmoid(y);
        out[(size_t)TTRG*BB*VV + step*BB + b] = pr;
        g_rate[b] = pr;
    }
}

// ---------------- init ----------------------------------------------------
__global__ void init_k(float* __restrict__ out, const int* __restrict__ trg_eid,
                       const float* __restrict__ trg_rate)
{
    long long i = (long long)blockIdx.x*blockDim.x + threadIdx.x;
    const long long RATE_OFF = (long long)TTRG*BB*VV;
    if (i < (long long)BB*VV) out[i] = 0.f;
    if (i < BB)               out[RATE_OFF + i] = 0.f;
    if (i < BB*HH)            g_h[i] = 0.f;
    if (i < BB){ g_eid[i] = trg_eid[i]; g_rate[i] = trg_rate[i]; }
}

// ---------------- launch ---------------------------------------------------
extern "C" void kernel_launch(void* const* d_in, const int* in_sizes, int n_in,
                              void* d_out, int out_size)
{
    const float* src      = (const float*)d_in[0];
    const int*   src_len  = (const int*)  d_in[1];
    const int*   trg_eid  = (const int*)  d_in[2];
    const float* trg_rate = (const float*)d_in[3];
    const float* emb      = (const float*)d_in[4];
    const float* enc_Wi   = (const float*)d_in[5];
    const float* enc_Wh   = (const float*)d_in[6];
    const float* enc_bi   = (const float*)d_in[7];
    const float* enc_bh   = (const float*)d_in[8];
    const float* dec_Wi   = (const float*)d_in[9];
    const float* dec_Wh   = (const float*)d_in[10];
    const float* dec_bi   = (const float*)d_in[11];
    const float* dec_bh   = (const float*)d_in[12];
    const float* We       = (const float*)d_in[13];
    const float* be       = (const float*)d_in[14];
    const float* W1       = (const float*)d_in[15];
    const float* b1       = (const float*)d_in[16];
    const float* W2       = (const float*)d_in[17];
    const float* b2       = (const float*)d_in[18];
    float* out = (float*)d_out;

    float *p_h, *p_h2, *p_gi_enc, *p_logits;
    cudaGetSymbolAddress((void**)&p_h,      g_h);
    cudaGetSymbolAddress((void**)&p_h2,     g_h2);
    cudaGetSymbolAddress((void**)&p_gi_enc, g_gi_enc);
    cudaGetSymbolAddress((void**)&p_logits, g_logits);

    float* hb[2] = {p_h, p_h2};
    int par = 0;

    init_k<<<10000,256>>>(out, trg_eid, trg_rate);

    sgemm_k<64,64,32,4,4><<<dim3(G3H/64, (TSRC*BB)/64), dim3(16,16)>>>(
        src, INDIM, enc_Wi, enc_bi, p_gi_enc, TSRC*BB, G3H, INDIM);

    // one-time (per replay) We bf16-plane precompute
    wsplit_k<<<NPAD, 256>>>(We);

    for (int t=0;t<TSRC;t++){
        gru_enc_f<<<dim3(HH/32, BB/16), 256>>>(
            hb[par], hb[par^1], enc_Wh, enc_bh,
            p_gi_enc + (size_t)t*BB*G3H, src_len, t);
        par ^= 1;
    }

    for (int step=1; step<TTRG; step++){
        gru_dec_f<<<dim3(HH/32, BB/16), 256>>>(
            hb[par], hb[par^1], dec_Wi, dec_bi, dec_Wh, dec_bh, emb);
        par ^= 1;
        vgemm_mma_k<<<NT2, 256>>>(be, p_logits);
        softrate_k<<<BB,256>>>(out, step, hb[par], emb, We, be,
                               W1, b1, W2, b2);
    }
}